// round 1
// baseline (speedup 1.0000x reference)
#include <cuda_runtime.h>
#include <math.h>

#define CIN   64
#define COUT  128
#define HIN   256
#define WIN   256
#define HP    64
#define WP    64
#define NP    4096      // HP*WP
#define BATCH 4
#define KELEM 16        // 4x4 kernel taps
#define KDIM  1024      // CIN*KELEM

// Scratch for Q/K/V activations: [B][O][N], fp32. 8 MB each.
__device__ float g_q[BATCH][COUT][NP];
__device__ float g_k[BATCH][COUT][NP];
__device__ float g_v[BATCH][COUT][NP];

// ---------------------------------------------------------------------------
// Phase 1: fused QKV patch-GEMM.
// One block handles: one batch b, one patch-row ph (64 patches), all 128 out
// channels, for q, k and v simultaneously (patches loaded once).
// 256 threads; thread og = t&15 owns channels {og*4..og*4+3, 64+og*4..+3},
// thread ng = t>>4 owns patches {ng*4..ng*4+3}.
// ---------------------------------------------------------------------------
__global__ __launch_bounds__(256, 1) void qkv_kernel(
    const float* __restrict__ x,
    const float* __restrict__ Wq, const float* __restrict__ bq,
    const float* __restrict__ Wk, const float* __restrict__ bk,
    const float* __restrict__ Wv, const float* __restrict__ bv)
{
    __shared__ float Ps[KELEM][64];        // one channel's 16 taps x 64 patches
    __shared__ float Ws[3][KELEM][COUT];   // q/k/v weight slice for this channel

    const int ph = blockIdx.x;
    const int b  = blockIdx.y;
    const int t  = threadIdx.x;
    const int og = t & 15;
    const int ng = t >> 4;
    const int n0 = ng * 4;
    const int oA = og * 4;
    const int oB = og * 4 + 64;

    float accq[8][4], acck[8][4], accv[8][4];
    #pragma unroll
    for (int i = 0; i < 8; ++i) {
        int o = (i < 4) ? (oA + i) : (oB + i - 4);
        float vq = bq[o], vk = bk[o], vv = bv[o];
        #pragma unroll
        for (int j = 0; j < 4; ++j) { accq[i][j] = vq; acck[i][j] = vk; accv[i][j] = vv; }
    }

    const float* xb = x + (size_t)b * CIN * HIN * WIN;

    for (int c = 0; c < CIN; ++c) {
        __syncthreads();
        // load patch chunk: Ps[k][n] = x[b, c, ph*4 + kh, n*4 + kw]
        #pragma unroll
        for (int i = 0; i < 4; ++i) {
            int idx = t + i * 256;          // 0..1023
            int k = idx >> 6, n = idx & 63;
            int kh = k >> 2, kw = k & 3;
            Ps[k][n] = xb[((size_t)c * HIN + ph * 4 + kh) * WIN + n * 4 + kw];
        }
        // load weight chunk: Ws[cv][k][o]
        #pragma unroll
        for (int i = 0; i < 8; ++i) {
            int idx = t + i * 256;          // 0..2047
            int o = idx >> 4, k = idx & 15;
            int gidx = o * KDIM + c * KELEM + k;
            Ws[0][k][o] = Wq[gidx];
            Ws[1][k][o] = Wk[gidx];
            Ws[2][k][o] = Wv[gidx];
        }
        __syncthreads();

        #pragma unroll
        for (int k = 0; k < KELEM; ++k) {
            float4 p4  = *(const float4*)&Ps[k][n0];
            float  pa[4] = {p4.x, p4.y, p4.z, p4.w};
            float4 qa4 = *(const float4*)&Ws[0][k][oA];
            float4 qb4 = *(const float4*)&Ws[0][k][oB];
            float4 ka4 = *(const float4*)&Ws[1][k][oA];
            float4 kb4 = *(const float4*)&Ws[1][k][oB];
            float4 va4 = *(const float4*)&Ws[2][k][oA];
            float4 vb4 = *(const float4*)&Ws[2][k][oB];
            float wq[8] = {qa4.x, qa4.y, qa4.z, qa4.w, qb4.x, qb4.y, qb4.z, qb4.w};
            float wk[8] = {ka4.x, ka4.y, ka4.z, ka4.w, kb4.x, kb4.y, kb4.z, kb4.w};
            float wv[8] = {va4.x, va4.y, va4.z, va4.w, vb4.x, vb4.y, vb4.z, vb4.w};
            #pragma unroll
            for (int i = 0; i < 8; ++i)
                #pragma unroll
                for (int j = 0; j < 4; ++j) {
                    accq[i][j] += wq[i] * pa[j];
                    acck[i][j] += wk[i] * pa[j];
                    accv[i][j] += wv[i] * pa[j];
                }
        }
    }

    const int nbase = ph * 64 + n0;
    #pragma unroll
    for (int i = 0; i < 8; ++i) {
        int o = (i < 4) ? (oA + i) : (oB + i - 4);
        *(float4*)&g_q[b][o][nbase] = make_float4(accq[i][0], accq[i][1], accq[i][2], accq[i][3]);
        *(float4*)&g_k[b][o][nbase] = make_float4(acck[i][0], acck[i][1], acck[i][2], acck[i][3]);
        *(float4*)&g_v[b][o][nbase] = make_float4(accv[i][0], accv[i][1], accv[i][2], accv[i][3]);
    }
}

// ---------------------------------------------------------------------------
// Phase 2: flash attention over N=4096, head dim 128, no scaling.
// One block: one batch b, one 64-query tile. Streams 64-key tiles.
// Dynamic smem layout (floats):
//   Qs  [128][64]          8192
//   KV  max(128*64, 64*132) = 8448   (K as [o][m], then V transposed [m][132])
//   S   [64][68]           4352      (scores, then probabilities)
//   alpha[64], mrow[64], lrow[64]
// ---------------------------------------------------------------------------
#define ATTN_SMEM_FLOATS (8192 + 8448 + 64*68 + 64*3)
#define ATTN_SMEM_BYTES  (ATTN_SMEM_FLOATS * 4)

__global__ __launch_bounds__(256, 2) void attn_kernel(float* __restrict__ out)
{
    extern __shared__ float sm[];
    float* Qs    = sm;               // 8192
    float* KV    = sm + 8192;        // 8448
    float* S     = KV + 8448;        // 4352
    float* alpha = S + 64 * 68;      // 64
    float* mrow  = alpha + 64;       // 64
    float* lrow  = mrow + 64;        // 64

    const int qt = blockIdx.x;
    const int b  = blockIdx.y;
    const int t  = threadIdx.x;
    const int og = t & 15;
    const int ng = t >> 4;
    const int n0 = ng * 4;           // 4 query rows
    const int m0 = og * 4;           // 4 key cols (S phase)
    const int oA = og * 4;           // 8 out channels, split halves (PV phase)
    const int oB = og * 4 + 64;

    // load Q tile: Qs[o][j] = q[b][o][qt*64+j]
    #pragma unroll
    for (int i = 0; i < 32; ++i) {
        int idx = t + i * 256;
        int o = idx >> 6, j = idx & 63;
        Qs[o * 64 + j] = g_q[b][o][qt * 64 + j];
    }
    if (t < 64) { mrow[t] = -1e30f; lrow[t] = 0.0f; }

    float acc[8][4];
    #pragma unroll
    for (int i = 0; i < 8; ++i)
        #pragma unroll
        for (int j = 0; j < 4; ++j) acc[i][j] = 0.0f;

    for (int mt = 0; mt < 64; ++mt) {
        __syncthreads();   // previous PV done with KV(V) and S(P)

        // load K tile: KV[o][m]
        #pragma unroll
        for (int i = 0; i < 32; ++i) {
            int idx = t + i * 256;
            int o = idx >> 6, m = idx & 63;
            KV[o * 64 + m] = g_k[b][o][mt * 64 + m];
        }
        __syncthreads();

        // S[n][m] = sum_o Q[o][n] * K[o][m]
        float s[4][4];
        #pragma unroll
        for (int i = 0; i < 4; ++i)
            #pragma unroll
            for (int j = 0; j < 4; ++j) s[i][j] = 0.0f;

        #pragma unroll 4
        for (int o = 0; o < 128; ++o) {
            float4 q4 = *(const float4*)&Qs[o * 64 + n0];
            float4 k4 = *(const float4*)&KV[o * 64 + m0];
            float qa[4] = {q4.x, q4.y, q4.z, q4.w};
            float ka[4] = {k4.x, k4.y, k4.z, k4.w};
            #pragma unroll
            for (int i = 0; i < 4; ++i)
                #pragma unroll
                for (int j = 0; j < 4; ++j) s[i][j] += qa[i] * ka[j];
        }
        #pragma unroll
        for (int i = 0; i < 4; ++i)
            *(float4*)&S[(n0 + i) * 68 + m0] = make_float4(s[i][0], s[i][1], s[i][2], s[i][3]);
        __syncthreads();

        // online softmax: 4 threads per row, 16 cols each
        {
            int rn = t >> 2, rl = t & 3;
            int base = rn * 68 + rl * 16;
            float mloc = -1e30f;
            #pragma unroll
            for (int j = 0; j < 16; ++j) mloc = fmaxf(mloc, S[base + j]);
            mloc = fmaxf(mloc, __shfl_xor_sync(0xffffffffu, mloc, 1));
            mloc = fmaxf(mloc, __shfl_xor_sync(0xffffffffu, mloc, 2));
            float mold = mrow[rn];
            float mnew = fmaxf(mold, mloc);
            float lsum = 0.0f;
            #pragma unroll
            for (int j = 0; j < 16; ++j) {
                float p = __expf(S[base + j] - mnew);
                S[base + j] = p;
                lsum += p;
            }
            lsum += __shfl_xor_sync(0xffffffffu, lsum, 1);
            lsum += __shfl_xor_sync(0xffffffffu, lsum, 2);
            if (rl == 0) {
                float a = __expf(mold - mnew);
                alpha[rn] = a;
                mrow[rn]  = mnew;
                lrow[rn]  = lrow[rn] * a + lsum;
            }
        }

        // load V tile transposed: KV[m][o] (stride 132), K no longer needed
        #pragma unroll
        for (int i = 0; i < 32; ++i) {
            int idx = t + i * 256;
            int o = idx >> 6, m = idx & 63;
            KV[m * 132 + o] = g_v[b][o][mt * 64 + m];
        }
        __syncthreads();   // P, alpha, V all ready

        // rescale + accumulate: acc[o][n] = acc*alpha[n] + sum_m P[n][m]*V[m][o]
        float av[4];
        #pragma unroll
        for (int j = 0; j < 4; ++j) av[j] = alpha[n0 + j];
        #pragma unroll
        for (int i = 0; i < 8; ++i)
            #pragma unroll
            for (int j = 0; j < 4; ++j) acc[i][j] *= av[j];

        #pragma unroll 4
        for (int m = 0; m < 64; ++m) {
            float4 vA = *(const float4*)&KV[m * 132 + oA];
            float4 vB = *(const float4*)&KV[m * 132 + oB];
            float va[8] = {vA.x, vA.y, vA.z, vA.w, vB.x, vB.y, vB.z, vB.w};
            float pp[4];
            #pragma unroll
            for (int j = 0; j < 4; ++j) pp[j] = S[(n0 + j) * 68 + m];
            #pragma unroll
            for (int i = 0; i < 8; ++i)
                #pragma unroll
                for (int j = 0; j < 4; ++j) acc[i][j] += va[i] * pp[j];
        }
    }

    // epilogue: divide by row sums, write out[b][o][n]
    float linv[4];
    #pragma unroll
    for (int j = 0; j < 4; ++j) linv[j] = 1.0f / lrow[n0 + j];

    const int nglob = qt * 64 + n0;
    #pragma unroll
    for (int i = 0; i < 8; ++i) {
        int o = (i < 4) ? (oA + i) : (oB + i - 4);
        float4 r = make_float4(acc[i][0] * linv[0], acc[i][1] * linv[1],
                               acc[i][2] * linv[2], acc[i][3] * linv[3]);
        *(float4*)&out[((size_t)b * COUT + o) * NP + nglob] = r;
    }
}

// ---------------------------------------------------------------------------
extern "C" void kernel_launch(void* const* d_in, const int* in_sizes, int n_in,
                              void* d_out, int out_size)
{
    (void)in_sizes; (void)n_in; (void)out_size;
    const float* x  = (const float*)d_in[0];
    const float* Wq = (const float*)d_in[1];
    const float* bq = (const float*)d_in[2];
    const float* Wk = (const float*)d_in[3];
    const float* bk = (const float*)d_in[4];
    const float* Wv = (const float*)d_in[5];
    const float* bv = (const float*)d_in[6];
    float* out = (float*)d_out;

    cudaFuncSetAttribute(attn_kernel, cudaFuncAttributeMaxDynamicSharedMemorySize,
                         ATTN_SMEM_BYTES);

    qkv_kernel<<<dim3(HP, BATCH), 256>>>(x, Wq, bq, Wk, bk, Wv, bv);
    attn_kernel<<<dim3(NP / 64, BATCH), 256, ATTN_SMEM_BYTES>>>(out);
}

// round 3
// speedup vs baseline: 1.9182x; 1.9182x over previous
#include <cuda_runtime.h>
#include <cuda_bf16.h>
#include <stdint.h>
#include <math.h>

#define CIN   64
#define COUT  128
#define HIN   256
#define WIN   256
#define NP    4096
#define BATCH 4
#define KELEM 16
#define KDIM  1024

// bf16 hi/lo splits: Q, K, V all stored [b][n][o] (row = token, col = channel)
__device__ __align__(128) __nv_bfloat16 gQh[BATCH][NP][COUT];
__device__ __align__(128) __nv_bfloat16 gQl[BATCH][NP][COUT];
__device__ __align__(128) __nv_bfloat16 gKh[BATCH][NP][COUT];
__device__ __align__(128) __nv_bfloat16 gKl[BATCH][NP][COUT];
__device__ __align__(128) __nv_bfloat16 gVh[BATCH][NP][COUT];
__device__ __align__(128) __nv_bfloat16 gVl[BATCH][NP][COUT];

// ---------------------------------------------------------------------------
// helpers
// ---------------------------------------------------------------------------
__device__ __forceinline__ uint32_t smem_u32(const void* p) {
    uint32_t a;
    asm("{ .reg .u64 t; cvta.to.shared.u64 t, %1; cvt.u32.u64 %0, t; }" : "=r"(a) : "l"(p));
    return a;
}
__device__ __forceinline__ void ldsm4(uint32_t r[4], uint32_t addr) {
    asm volatile("ldmatrix.sync.aligned.m8n8.x4.shared.b16 {%0,%1,%2,%3}, [%4];"
                 : "=r"(r[0]), "=r"(r[1]), "=r"(r[2]), "=r"(r[3]) : "r"(addr));
}
__device__ __forceinline__ void ldsm4t(uint32_t r[4], uint32_t addr) {
    asm volatile("ldmatrix.sync.aligned.m8n8.x4.trans.shared.b16 {%0,%1,%2,%3}, [%4];"
                 : "=r"(r[0]), "=r"(r[1]), "=r"(r[2]), "=r"(r[3]) : "r"(addr));
}
__device__ __forceinline__ void mma_bf16(float d[4], const uint32_t a[4],
                                         uint32_t b0, uint32_t b1) {
    asm volatile("mma.sync.aligned.m16n8k16.row.col.f32.bf16.bf16.f32 "
                 "{%0,%1,%2,%3}, {%4,%5,%6,%7}, {%8,%9}, {%0,%1,%2,%3};"
                 : "+f"(d[0]), "+f"(d[1]), "+f"(d[2]), "+f"(d[3])
                 : "r"(a[0]), "r"(a[1]), "r"(a[2]), "r"(a[3]), "r"(b0), "r"(b1));
}
__device__ __forceinline__ void cpasync16(uint32_t dst, const void* src) {
    asm volatile("cp.async.cg.shared.global [%0], [%1], 16;" :: "r"(dst), "l"(src));
}
#define CP_COMMIT() asm volatile("cp.async.commit_group;" ::: "memory")
#define CP_WAIT1()  asm volatile("cp.async.wait_group 1;" ::: "memory")
#define CP_WAIT0()  asm volatile("cp.async.wait_group 0;" ::: "memory")

__device__ __forceinline__ uint32_t pack_bf2(__nv_bfloat16 a, __nv_bfloat16 b) {
    return ((uint32_t)__bfloat16_as_ushort(b) << 16) | (uint32_t)__bfloat16_as_ushort(a);
}
// split (x,y) into packed bf16 hi and lo pairs (low half = x)
__device__ __forceinline__ void split2(float x, float y, uint32_t& h, uint32_t& l) {
    __nv_bfloat16 hx = __float2bfloat16(x), hy = __float2bfloat16(y);
    h = pack_bf2(hx, hy);
    l = pack_bf2(__float2bfloat16(x - __bfloat162float(hx)),
                 __float2bfloat16(y - __bfloat162float(hy)));
}
__device__ __forceinline__ void store4_hl(__nv_bfloat16* ph, __nv_bfloat16* pl,
                                          float a, float b, float c, float d) {
    uint32_t h0, l0, h1, l1;
    split2(a, b, h0, l0);
    split2(c, d, h1, l1);
    *(uint2*)ph = make_uint2(h0, h1);
    *(uint2*)pl = make_uint2(l0, l1);
}

// ---------------------------------------------------------------------------
// Phase 1: fused QKV patch-GEMM (SIMT), emits bf16 hi/lo, all [b][n][o]
// ---------------------------------------------------------------------------
__global__ __launch_bounds__(256, 1) void qkv_kernel(
    const float* __restrict__ x,
    const float* __restrict__ Wq, const float* __restrict__ bq,
    const float* __restrict__ Wk, const float* __restrict__ bk,
    const float* __restrict__ Wv, const float* __restrict__ bv)
{
    __shared__ float Ps[KELEM][64];
    __shared__ float Ws[3][KELEM][COUT];

    const int ph = blockIdx.x;
    const int b  = blockIdx.y;
    const int t  = threadIdx.x;
    const int og = t & 15;
    const int ng = t >> 4;
    const int n0 = ng * 4;
    const int oA = og * 4;
    const int oB = og * 4 + 64;

    float accq[8][4], acck[8][4], accv[8][4];
    #pragma unroll
    for (int i = 0; i < 8; ++i) {
        int o = (i < 4) ? (oA + i) : (oB + i - 4);
        float vq = bq[o], vk = bk[o], vv = bv[o];
        #pragma unroll
        for (int j = 0; j < 4; ++j) { accq[i][j] = vq; acck[i][j] = vk; accv[i][j] = vv; }
    }

    const float* xb = x + (size_t)b * CIN * HIN * WIN;

    for (int c = 0; c < CIN; ++c) {
        __syncthreads();
        #pragma unroll
        for (int i = 0; i < 4; ++i) {
            int idx = t + i * 256;
            int k = idx >> 6, n = idx & 63;
            int kh = k >> 2, kw = k & 3;
            Ps[k][n] = xb[((size_t)c * HIN + ph * 4 + kh) * WIN + n * 4 + kw];
        }
        #pragma unroll
        for (int i = 0; i < 8; ++i) {
            int idx = t + i * 256;
            int o = idx >> 4, k = idx & 15;
            int gidx = o * KDIM + c * KELEM + k;
            Ws[0][k][o] = Wq[gidx];
            Ws[1][k][o] = Wk[gidx];
            Ws[2][k][o] = Wv[gidx];
        }
        __syncthreads();

        #pragma unroll
        for (int k = 0; k < KELEM; ++k) {
            float4 p4  = *(const float4*)&Ps[k][n0];
            float  pa[4] = {p4.x, p4.y, p4.z, p4.w};
            float4 qa4 = *(const float4*)&Ws[0][k][oA];
            float4 qb4 = *(const float4*)&Ws[0][k][oB];
            float4 ka4 = *(const float4*)&Ws[1][k][oA];
            float4 kb4 = *(const float4*)&Ws[1][k][oB];
            float4 va4 = *(const float4*)&Ws[2][k][oA];
            float4 vb4 = *(const float4*)&Ws[2][k][oB];
            float wq[8] = {qa4.x, qa4.y, qa4.z, qa4.w, qb4.x, qb4.y, qb4.z, qb4.w};
            float wk[8] = {ka4.x, ka4.y, ka4.z, ka4.w, kb4.x, kb4.y, kb4.z, kb4.w};
            float wv[8] = {va4.x, va4.y, va4.z, va4.w, vb4.x, vb4.y, vb4.z, vb4.w};
            #pragma unroll
            for (int i = 0; i < 8; ++i)
                #pragma unroll
                for (int j = 0; j < 4; ++j) {
                    accq[i][j] += wq[i] * pa[j];
                    acck[i][j] += wk[i] * pa[j];
                    accv[i][j] += wv[i] * pa[j];
                }
        }
    }

    const int nbase = ph * 64 + n0;
    #pragma unroll
    for (int j = 0; j < 4; ++j) {
        int n = nbase + j;
        store4_hl(&gQh[b][n][oA], &gQl[b][n][oA], accq[0][j], accq[1][j], accq[2][j], accq[3][j]);
        store4_hl(&gQh[b][n][oB], &gQl[b][n][oB], accq[4][j], accq[5][j], accq[6][j], accq[7][j]);
        store4_hl(&gKh[b][n][oA], &gKl[b][n][oA], acck[0][j], acck[1][j], acck[2][j], acck[3][j]);
        store4_hl(&gKh[b][n][oB], &gKl[b][n][oB], acck[4][j], acck[5][j], acck[6][j], acck[7][j]);
        store4_hl(&gVh[b][n][oA], &gVl[b][n][oA], accv[0][j], accv[1][j], accv[2][j], accv[3][j]);
        store4_hl(&gVh[b][n][oB], &gVl[b][n][oB], accv[4][j], accv[5][j], accv[6][j], accv[7][j]);
    }
}

// ---------------------------------------------------------------------------
// Phase 2: FlashAttention-2 with mma.sync bf16 (x3 split), cp.async pipeline.
// CTA: 128-query tile x batch. 8 warps, 16 query rows per warp.
// smem tiles: rows of 128 bf16 padded to 272 B (conflict-free ldmatrix).
// ---------------------------------------------------------------------------
#define TPITCH 272
#define TBYTES (128 * TPITCH)   // 34816 per tile

// async copy of a [128 x 128] bf16 tile (gmem rows of 128) into padded smem
__device__ __forceinline__ void tile_async(uint32_t sdst, const __nv_bfloat16* __restrict__ g, int t) {
    #pragma unroll
    for (int i = 0; i < 8; ++i) {
        int idx = t + i * 256;
        int row = idx >> 4, c = idx & 15;
        cpasync16(sdst + row * TPITCH + c * 16, g + row * 128 + c * 8);
    }
}

__global__ __launch_bounds__(256, 1) void attn_kernel(float* __restrict__ out)
{
    extern __shared__ __align__(128) char sb[];
    const uint32_t aQh = smem_u32(sb);
    const uint32_t aQl = aQh + TBYTES;
    const uint32_t aKh = aQh + 2 * TBYTES;
    const uint32_t aKl = aQh + 3 * TBYTES;
    const uint32_t aVh = aQh + 4 * TBYTES;
    const uint32_t aVl = aQh + 5 * TBYTES;

    const int qt = blockIdx.x, b = blockIdx.y;
    const int t = threadIdx.x, lane = t & 31, wid = t >> 5;
    const int n0 = wid * 16;

    const __nv_bfloat16* pKh = &gKh[b][0][0];
    const __nv_bfloat16* pKl = &gKl[b][0][0];
    const __nv_bfloat16* pVh = &gVh[b][0][0];
    const __nv_bfloat16* pVl = &gVl[b][0][0];

    // prefetch K0 then V0
    tile_async(aKh, pKh, t);
    tile_async(aKl, pKl, t);
    CP_COMMIT();
    tile_async(aVh, pVh, t);
    tile_async(aVl, pVl, t);
    CP_COMMIT();

    // load Q (hi/lo) into smem
    {
        const __nv_bfloat16* gq = &gQh[b][qt * 128][0];
        const __nv_bfloat16* gl = &gQl[b][qt * 128][0];
        #pragma unroll
        for (int i = 0; i < 8; ++i) {
            int idx = t + i * 256;
            int row = idx >> 4, c = idx & 15;
            *(uint4*)(sb + row * TPITCH + c * 16) = *(const uint4*)(gq + row * 128 + c * 8);
            *(uint4*)(sb + TBYTES + row * TPITCH + c * 16) = *(const uint4*)(gl + row * 128 + c * 8);
        }
    }

    float S[16][4], O[16][4];
    #pragma unroll
    for (int j = 0; j < 16; ++j)
        #pragma unroll
        for (int c = 0; c < 4; ++c) O[j][c] = 0.0f;
    float m0 = -1e30f, m1 = -1e30f, l0 = 0.0f, l1 = 0.0f;

    // precomputed ldmatrix address offsets (within-tile)
    const uint32_t offA = (uint32_t)(n0 + (lane & 15)) * TPITCH + (lane >> 4) * 16;
    const uint32_t offB_row = (uint32_t)((lane & 7) + ((lane >> 4) & 1) * 8) * TPITCH +
                              ((lane >> 3) & 1) * 16;                       // + ng*16*TPITCH + kc*32
    const uint32_t offV_row = (uint32_t)((lane & 7) + ((lane >> 3) & 1) * 8) * TPITCH +
                              (lane >> 4) * 16;                             // + mc*16*TPITCH + og*32

    #pragma unroll 1
    for (int mt = 0; mt < 32; ++mt) {
        CP_WAIT1();            // K_mt resident (V_mt may still be in flight)
        __syncthreads();

        // ---- S = Qh*Kh + Qh*Kl + Ql*Kh ----
        #pragma unroll
        for (int j = 0; j < 16; ++j)
            #pragma unroll
            for (int c = 0; c < 4; ++c) S[j][c] = 0.0f;

        #pragma unroll 1
        for (int kc = 0; kc < 8; ++kc) {
            uint32_t qh[4], ql[4];
            ldsm4(qh, aQh + offA + kc * 32);
            ldsm4(ql, aQl + offA + kc * 32);
            #pragma unroll
            for (int ng = 0; ng < 8; ++ng) {
                uint32_t bh[4], bl[4];
                uint32_t ro = (uint32_t)ng * 16 * TPITCH + offB_row + kc * 32;
                ldsm4(bh, aKh + ro);
                ldsm4(bl, aKl + ro);
                mma_bf16(S[2 * ng],     qh, bh[0], bh[1]);
                mma_bf16(S[2 * ng + 1], qh, bh[2], bh[3]);
                mma_bf16(S[2 * ng],     qh, bl[0], bl[1]);
                mma_bf16(S[2 * ng + 1], qh, bl[2], bl[3]);
                mma_bf16(S[2 * ng],     ql, bh[0], bh[1]);
                mma_bf16(S[2 * ng + 1], ql, bh[2], bh[3]);
            }
        }
        __syncthreads();        // K consumed by all warps

        if (mt < 31) {          // prefetch K_{mt+1} (overlaps softmax + PV)
            tile_async(aKh, pKh + (size_t)(mt + 1) * 128 * 128, t);
            tile_async(aKl, pKl + (size_t)(mt + 1) * 128 * 128, t);
            CP_COMMIT();
        }

        // ---- online softmax (registers only) ----
        {
            float mx0 = -1e30f, mx1 = -1e30f;
            #pragma unroll
            for (int j = 0; j < 16; ++j) {
                mx0 = fmaxf(mx0, fmaxf(S[j][0], S[j][1]));
                mx1 = fmaxf(mx1, fmaxf(S[j][2], S[j][3]));
            }
            mx0 = fmaxf(mx0, __shfl_xor_sync(0xffffffffu, mx0, 1));
            mx0 = fmaxf(mx0, __shfl_xor_sync(0xffffffffu, mx0, 2));
            mx1 = fmaxf(mx1, __shfl_xor_sync(0xffffffffu, mx1, 1));
            mx1 = fmaxf(mx1, __shfl_xor_sync(0xffffffffu, mx1, 2));
            float mn0 = fmaxf(m0, mx0), mn1 = fmaxf(m1, mx1);
            float a0 = __expf(m0 - mn0), a1 = __expf(m1 - mn1);
            m0 = mn0; m1 = mn1;
            float ls0 = 0.0f, ls1 = 0.0f;
            #pragma unroll
            for (int j = 0; j < 16; ++j) {
                S[j][0] = __expf(S[j][0] - mn0); ls0 += S[j][0];
                S[j][1] = __expf(S[j][1] - mn0); ls0 += S[j][1];
                S[j][2] = __expf(S[j][2] - mn1); ls1 += S[j][2];
                S[j][3] = __expf(S[j][3] - mn1); ls1 += S[j][3];
                O[j][0] *= a0; O[j][1] *= a0; O[j][2] *= a1; O[j][3] *= a1;
            }
            ls0 += __shfl_xor_sync(0xffffffffu, ls0, 1);
            ls0 += __shfl_xor_sync(0xffffffffu, ls0, 2);
            ls1 += __shfl_xor_sync(0xffffffffu, ls1, 1);
            ls1 += __shfl_xor_sync(0xffffffffu, ls1, 2);
            l0 = l0 * a0 + ls0;
            l1 = l1 * a1 + ls1;
        }

        if (mt < 31) { CP_WAIT1(); } else { CP_WAIT0(); }   // V_mt resident
        __syncthreads();

        // ---- O += Ph*Vh + Ph*Vl + Pl*Vh ----
        #pragma unroll
        for (int kc = 0; kc < 8; ++kc) {
            uint32_t ah[4], al[4];
            split2(S[2 * kc][0],     S[2 * kc][1],     ah[0], al[0]);
            split2(S[2 * kc][2],     S[2 * kc][3],     ah[1], al[1]);
            split2(S[2 * kc + 1][0], S[2 * kc + 1][1], ah[2], al[2]);
            split2(S[2 * kc + 1][2], S[2 * kc + 1][3], ah[3], al[3]);
            #pragma unroll
            for (int og = 0; og < 8; ++og) {
                uint32_t vh[4], vl[4];
                uint32_t ro = (uint32_t)kc * 16 * TPITCH + offV_row + og * 32;
                ldsm4t(vh, aVh + ro);
                ldsm4t(vl, aVl + ro);
                mma_bf16(O[2 * og],     ah, vh[0], vh[1]);
                mma_bf16(O[2 * og + 1], ah, vh[2], vh[3]);
                mma_bf16(O[2 * og],     ah, vl[0], vl[1]);
                mma_bf16(O[2 * og + 1], ah, vl[2], vl[3]);
                mma_bf16(O[2 * og],     al, vh[0], vh[1]);
                mma_bf16(O[2 * og + 1], al, vh[2], vh[3]);
            }
        }
        __syncthreads();        // V consumed

        if (mt < 31) {          // prefetch V_{mt+1} (overlaps next S)
            tile_async(aVh, pVh + (size_t)(mt + 1) * 128 * 128, t);
            tile_async(aVl, pVl + (size_t)(mt + 1) * 128 * 128, t);
            CP_COMMIT();
        }
    }

    // ---- epilogue ----
    const float i0 = 1.0f / l0, i1 = 1.0f / l1;
    const int nbase = qt * 128 + n0 + (lane >> 2);
    #pragma unroll
    for (int j = 0; j < 16; ++j) {
        int o = j * 8 + (lane & 3) * 2;
        float* p0 = out + ((size_t)(b * COUT + o)) * NP + nbase;
        float* p1 = out + ((size_t)(b * COUT + o + 1)) * NP + nbase;
        p0[0] = O[j][0] * i0;
        p1[0] = O[j][1] * i0;
        p0[8] = O[j][2] * i1;
        p1[8] = O[j][3] * i1;
    }
}

// ---------------------------------------------------------------------------
extern "C" void kernel_launch(void* const* d_in, const int* in_sizes, int n_in,
                              void* d_out, int out_size)
{
    (void)in_sizes; (void)n_in; (void)out_size;
    const float* x  = (const float*)d_in[0];
    const float* Wq = (const float*)d_in[1];
    const float* bq = (const float*)d_in[2];
    const float* Wk = (const float*)d_in[3];
    const float* bk = (const float*)d_in[4];
    const float* Wv = (const float*)d_in[5];
    const float* bv = (const float*)d_in[6];
    float* out = (float*)d_out;

    cudaFuncSetAttribute(attn_kernel, cudaFuncAttributeMaxDynamicSharedMemorySize,
                         6 * TBYTES + 256);

    qkv_kernel<<<dim3(64, BATCH), 256>>>(x, Wq, bq, Wk, bk, Wv, bv);
    attn_kernel<<<dim3(32, BATCH), 256, 6 * TBYTES + 256>>>(out);
}

// round 4
// speedup vs baseline: 3.5212x; 1.8357x over previous
#include <cuda_runtime.h>
#include <cuda_bf16.h>
#include <stdint.h>
#include <math.h>

#define CIN   64
#define COUT  128
#define HIN   256
#define WIN   256
#define NP    4096
#define BATCH 4
#define KDIM  1024

// bf16 hi/lo splits: Q, K, V all stored [b][n][o] (row = token, col = channel)
__device__ __align__(128) __nv_bfloat16 gQh[BATCH][NP][COUT];
__device__ __align__(128) __nv_bfloat16 gQl[BATCH][NP][COUT];
__device__ __align__(128) __nv_bfloat16 gKh[BATCH][NP][COUT];
__device__ __align__(128) __nv_bfloat16 gKl[BATCH][NP][COUT];
__device__ __align__(128) __nv_bfloat16 gVh[BATCH][NP][COUT];
__device__ __align__(128) __nv_bfloat16 gVl[BATCH][NP][COUT];
// im2col activations [b][n][ck] and split weights [mat][o][ck]
__device__ __align__(128) __nv_bfloat16 gAh[BATCH][NP][KDIM];
__device__ __align__(128) __nv_bfloat16 gAl[BATCH][NP][KDIM];
__device__ __align__(128) __nv_bfloat16 gWh[3][COUT][KDIM];
__device__ __align__(128) __nv_bfloat16 gWl[3][COUT][KDIM];

// ---------------------------------------------------------------------------
// helpers
// ---------------------------------------------------------------------------
__device__ __forceinline__ uint32_t smem_u32(const void* p) {
    uint32_t a;
    asm("{ .reg .u64 t; cvta.to.shared.u64 t, %1; cvt.u32.u64 %0, t; }" : "=r"(a) : "l"(p));
    return a;
}
__device__ __forceinline__ void ldsm4(uint32_t r[4], uint32_t addr) {
    asm volatile("ldmatrix.sync.aligned.m8n8.x4.shared.b16 {%0,%1,%2,%3}, [%4];"
                 : "=r"(r[0]), "=r"(r[1]), "=r"(r[2]), "=r"(r[3]) : "r"(addr));
}
__device__ __forceinline__ void ldsm4t(uint32_t r[4], uint32_t addr) {
    asm volatile("ldmatrix.sync.aligned.m8n8.x4.trans.shared.b16 {%0,%1,%2,%3}, [%4];"
                 : "=r"(r[0]), "=r"(r[1]), "=r"(r[2]), "=r"(r[3]) : "r"(addr));
}
__device__ __forceinline__ void mma_bf16(float d[4], const uint32_t a[4],
                                         uint32_t b0, uint32_t b1) {
    asm volatile("mma.sync.aligned.m16n8k16.row.col.f32.bf16.bf16.f32 "
                 "{%0,%1,%2,%3}, {%4,%5,%6,%7}, {%8,%9}, {%0,%1,%2,%3};"
                 : "+f"(d[0]), "+f"(d[1]), "+f"(d[2]), "+f"(d[3])
                 : "r"(a[0]), "r"(a[1]), "r"(a[2]), "r"(a[3]), "r"(b0), "r"(b1));
}
__device__ __forceinline__ void cpasync16(uint32_t dst, const void* src) {
    asm volatile("cp.async.cg.shared.global [%0], [%1], 16;" :: "r"(dst), "l"(src));
}
#define CP_COMMIT() asm volatile("cp.async.commit_group;" ::: "memory")
#define CP_WAIT1()  asm volatile("cp.async.wait_group 1;" ::: "memory")
#define CP_WAIT0()  asm volatile("cp.async.wait_group 0;" ::: "memory")

__device__ __forceinline__ uint32_t pack_bf2(__nv_bfloat16 a, __nv_bfloat16 b) {
    return ((uint32_t)__bfloat16_as_ushort(b) << 16) | (uint32_t)__bfloat16_as_ushort(a);
}
__device__ __forceinline__ void split2(float x, float y, uint32_t& h, uint32_t& l) {
    __nv_bfloat16 hx = __float2bfloat16(x), hy = __float2bfloat16(y);
    h = pack_bf2(hx, hy);
    l = pack_bf2(__float2bfloat16(x - __bfloat162float(hx)),
                 __float2bfloat16(y - __bfloat162float(hy)));
}

// ---------------------------------------------------------------------------
// Pass 0a: split W (OIHW flattened = [o][1024] K-major) into bf16 hi/lo
// grid (128, 3), 256 threads; thread handles 4 consecutive k
// ---------------------------------------------------------------------------
__global__ void wsplit_kernel(const float* __restrict__ Wq,
                              const float* __restrict__ Wk,
                              const float* __restrict__ Wv)
{
    const int o = blockIdx.x, mat = blockIdx.y, t = threadIdx.x;
    const float* W = (mat == 0) ? Wq : (mat == 1) ? Wk : Wv;
    float4 w = *(const float4*)(W + o * KDIM + t * 4);
    uint32_t h0, l0, h1, l1;
    split2(w.x, w.y, h0, l0);
    split2(w.z, w.w, h1, l1);
    *(uint2*)&gWh[mat][o][t * 4] = make_uint2(h0, h1);
    *(uint2*)&gWl[mat][o][t * 4] = make_uint2(l0, l1);
}

// ---------------------------------------------------------------------------
// Pass 0b: im2col + split. A[b][ph*64+pw][c*16 + kh*4 + kw] = x[b][c][ph*4+kh][pw*4+kw]
// grid (16, 64, 4) = (ph/4, c, b); 256 threads = pw(64) x phl(4)
// ---------------------------------------------------------------------------
__global__ void im2col_kernel(const float* __restrict__ x)
{
    const int pw = threadIdx.x & 63;
    const int ph = blockIdx.x * 4 + (threadIdx.x >> 6);
    const int c = blockIdx.y, b = blockIdx.z;
    const float* xp = x + (((size_t)(b * CIN + c) * HIN + ph * 4) * WIN + pw * 4);
    uint32_t h[8], l[8];
    #pragma unroll
    for (int kh = 0; kh < 4; ++kh) {
        float4 v = *(const float4*)(xp + kh * WIN);
        split2(v.x, v.y, h[kh * 2], l[kh * 2]);
        split2(v.z, v.w, h[kh * 2 + 1], l[kh * 2 + 1]);
    }
    const int n = ph * 64 + pw;
    *(uint4*)&gAh[b][n][c * 16]     = make_uint4(h[0], h[1], h[2], h[3]);
    *(uint4*)&gAh[b][n][c * 16 + 8] = make_uint4(h[4], h[5], h[6], h[7]);
    *(uint4*)&gAl[b][n][c * 16]     = make_uint4(l[0], l[1], l[2], l[3]);
    *(uint4*)&gAl[b][n][c * 16 + 8] = make_uint4(l[4], l[5], l[6], l[7]);
}

// ---------------------------------------------------------------------------
// Pass 1: QKV GEMM via mma.sync bf16x3. grid (ntile=32, b=4, mat=3).
// CTA 256 threads, 8 warps; warp = 16 patch rows x all 128 Cout.
// K pipeline: KC=64, 2 stages, cp.async.
// ---------------------------------------------------------------------------
#define GP 144                      // smem pitch bytes for 64-bf16 rows
#define GTILE (128 * GP)            // 18432 B per tile
#define GSTAGE (4 * GTILE)          // Ah, Al, Wh, Wl

__device__ __forceinline__ void gchunk_async(uint32_t sbase,
                                             const __nv_bfloat16* __restrict__ gA_h,
                                             const __nv_bfloat16* __restrict__ gA_l,
                                             const __nv_bfloat16* __restrict__ gW_h,
                                             const __nv_bfloat16* __restrict__ gW_l,
                                             int kc0, int t)
{
    #pragma unroll
    for (int i = 0; i < 4; ++i) {
        int idx = t + i * 256;
        int row = idx >> 3, cs = idx & 7;
        uint32_t d = sbase + row * GP + cs * 16;
        size_t s = (size_t)row * KDIM + kc0 + cs * 8;
        cpasync16(d,              gA_h + s);
        cpasync16(d + GTILE,      gA_l + s);
        cpasync16(d + 2 * GTILE,  gW_h + s);
        cpasync16(d + 3 * GTILE,  gW_l + s);
    }
}

__global__ __launch_bounds__(256, 1) void qkv_mma_kernel(
    const float* __restrict__ bq, const float* __restrict__ bk,
    const float* __restrict__ bv)
{
    extern __shared__ __align__(128) char sb[];
    const uint32_t s0 = smem_u32(sb);

    const int nt = blockIdx.x, b = blockIdx.y, mat = blockIdx.z;
    const int t = threadIdx.x, lane = t & 31, wid = t >> 5;
    const int n0 = wid * 16;

    const __nv_bfloat16* pAh = &gAh[b][nt * 128][0];
    const __nv_bfloat16* pAl = &gAl[b][nt * 128][0];
    const __nv_bfloat16* pWh = &gWh[mat][0][0];
    const __nv_bfloat16* pWl = &gWl[mat][0][0];
    const float* bias = (mat == 0) ? bq : (mat == 1) ? bk : bv;

    gchunk_async(s0,          pAh, pAl, pWh, pWl, 0, t);
    CP_COMMIT();
    gchunk_async(s0 + GSTAGE, pAh, pAl, pWh, pWl, 64, t);
    CP_COMMIT();

    float S[16][4];
    #pragma unroll
    for (int j = 0; j < 16; ++j)
        #pragma unroll
        for (int c = 0; c < 4; ++c) S[j][c] = 0.0f;

    const uint32_t offA = (uint32_t)(n0 + (lane & 15)) * GP + (lane >> 4) * 16;
    const uint32_t offB = (uint32_t)((lane & 7) + ((lane >> 4) & 1) * 8) * GP +
                          ((lane >> 3) & 1) * 16;

    #pragma unroll 1
    for (int ch = 0; ch < 16; ++ch) {
        if (ch < 15) { CP_WAIT1(); } else { CP_WAIT0(); }
        __syncthreads();
        const uint32_t st = s0 + (ch & 1) * GSTAGE;
        const uint32_t aA = st, aAl = st + GTILE, aW = st + 2 * GTILE, aWl = st + 3 * GTILE;

        #pragma unroll
        for (int kc = 0; kc < 4; ++kc) {
            uint32_t ah[4], al[4];
            ldsm4(ah, aA + offA + kc * 32);
            ldsm4(al, aAl + offA + kc * 32);
            #pragma unroll
            for (int og = 0; og < 8; ++og) {
                uint32_t bh[4], bl[4];
                uint32_t ro = (uint32_t)og * 16 * GP + offB + kc * 32;
                ldsm4(bh, aW + ro);
                ldsm4(bl, aWl + ro);
                mma_bf16(S[2 * og],     ah, bh[0], bh[1]);
                mma_bf16(S[2 * og + 1], ah, bh[2], bh[3]);
                mma_bf16(S[2 * og],     ah, bl[0], bl[1]);
                mma_bf16(S[2 * og + 1], ah, bl[2], bl[3]);
                mma_bf16(S[2 * og],     al, bh[0], bh[1]);
                mma_bf16(S[2 * og + 1], al, bh[2], bh[3]);
            }
        }
        __syncthreads();
        if (ch < 14) {
            gchunk_async(s0 + (ch & 1) * GSTAGE, pAh, pAl, pWh, pWl, (ch + 2) * 64, t);
            CP_COMMIT();
        }
    }

    // epilogue: add bias, split hi/lo, store [b][n][o]
    __nv_bfloat16* outh = (mat == 0) ? &gQh[b][0][0] : (mat == 1) ? &gKh[b][0][0] : &gVh[b][0][0];
    __nv_bfloat16* outl = (mat == 0) ? &gQl[b][0][0] : (mat == 1) ? &gKl[b][0][0] : &gVl[b][0][0];
    const int na = nt * 128 + n0 + (lane >> 2);
    #pragma unroll
    for (int j = 0; j < 16; ++j) {
        int o = j * 8 + (lane & 3) * 2;
        float b0 = bias[o], b1 = bias[o + 1];
        uint32_t h, l;
        split2(S[j][0] + b0, S[j][1] + b1, h, l);
        *(uint32_t*)(outh + (size_t)na * COUT + o) = h;
        *(uint32_t*)(outl + (size_t)na * COUT + o) = l;
        split2(S[j][2] + b0, S[j][3] + b1, h, l);
        *(uint32_t*)(outh + (size_t)(na + 8) * COUT + o) = h;
        *(uint32_t*)(outl + (size_t)(na + 8) * COUT + o) = l;
    }
}

// ---------------------------------------------------------------------------
// Phase 2: FlashAttention-2 with mma.sync bf16 (x3 split) — unchanged from R3.
// ---------------------------------------------------------------------------
#define TPITCH 272
#define TBYTES (128 * TPITCH)

__device__ __forceinline__ void tile_async(uint32_t sdst, const __nv_bfloat16* __restrict__ g, int t) {
    #pragma unroll
    for (int i = 0; i < 8; ++i) {
        int idx = t + i * 256;
        int row = idx >> 4, c = idx & 15;
        cpasync16(sdst + row * TPITCH + c * 16, g + row * 128 + c * 8);
    }
}

__global__ __launch_bounds__(256, 1) void attn_kernel(float* __restrict__ out)
{
    extern __shared__ __align__(128) char sb[];
    const uint32_t aQh = smem_u32(sb);
    const uint32_t aQl = aQh + TBYTES;
    const uint32_t aKh = aQh + 2 * TBYTES;
    const uint32_t aKl = aQh + 3 * TBYTES;
    const uint32_t aVh = aQh + 4 * TBYTES;
    const uint32_t aVl = aQh + 5 * TBYTES;

    const int qt = blockIdx.x, b = blockIdx.y;
    const int t = threadIdx.x, lane = t & 31, wid = t >> 5;
    const int n0 = wid * 16;

    const __nv_bfloat16* pKh = &gKh[b][0][0];
    const __nv_bfloat16* pKl = &gKl[b][0][0];
    const __nv_bfloat16* pVh = &gVh[b][0][0];
    const __nv_bfloat16* pVl = &gVl[b][0][0];

    tile_async(aKh, pKh, t);
    tile_async(aKl, pKl, t);
    CP_COMMIT();
    tile_async(aVh, pVh, t);
    tile_async(aVl, pVl, t);
    CP_COMMIT();

    {
        const __nv_bfloat16* gq = &gQh[b][qt * 128][0];
        const __nv_bfloat16* gl = &gQl[b][qt * 128][0];
        #pragma unroll
        for (int i = 0; i < 8; ++i) {
            int idx = t + i * 256;
            int row = idx >> 4, c = idx & 15;
            *(uint4*)(sb + row * TPITCH + c * 16) = *(const uint4*)(gq + row * 128 + c * 8);
            *(uint4*)(sb + TBYTES + row * TPITCH + c * 16) = *(const uint4*)(gl + row * 128 + c * 8);
        }
    }

    float S[16][4], O[16][4];
    #pragma unroll
    for (int j = 0; j < 16; ++j)
        #pragma unroll
        for (int c = 0; c < 4; ++c) O[j][c] = 0.0f;
    float m0 = -1e30f, m1 = -1e30f, l0 = 0.0f, l1 = 0.0f;

    const uint32_t offA = (uint32_t)(n0 + (lane & 15)) * TPITCH + (lane >> 4) * 16;
    const uint32_t offB_row = (uint32_t)((lane & 7) + ((lane >> 4) & 1) * 8) * TPITCH +
                              ((lane >> 3) & 1) * 16;
    const uint32_t offV_row = (uint32_t)((lane & 7) + ((lane >> 3) & 1) * 8) * TPITCH +
                              (lane >> 4) * 16;

    #pragma unroll 1
    for (int mt = 0; mt < 32; ++mt) {
        CP_WAIT1();
        __syncthreads();

        #pragma unroll
        for (int j = 0; j < 16; ++j)
            #pragma unroll
            for (int c = 0; c < 4; ++c) S[j][c] = 0.0f;

        #pragma unroll 1
        for (int kc = 0; kc < 8; ++kc) {
            uint32_t qh[4], ql[4];
            ldsm4(qh, aQh + offA + kc * 32);
            ldsm4(ql, aQl + offA + kc * 32);
            #pragma unroll
            for (int ng = 0; ng < 8; ++ng) {
                uint32_t bh[4], bl[4];
                uint32_t ro = (uint32_t)ng * 16 * TPITCH + offB_row + kc * 32;
                ldsm4(bh, aKh + ro);
                ldsm4(bl, aKl + ro);
                mma_bf16(S[2 * ng],     qh, bh[0], bh[1]);
                mma_bf16(S[2 * ng + 1], qh, bh[2], bh[3]);
                mma_bf16(S[2 * ng],     qh, bl[0], bl[1]);
                mma_bf16(S[2 * ng + 1], qh, bl[2], bl[3]);
                mma_bf16(S[2 * ng],     ql, bh[0], bh[1]);
                mma_bf16(S[2 * ng + 1], ql, bh[2], bh[3]);
            }
        }
        __syncthreads();

        if (mt < 31) {
            tile_async(aKh, pKh + (size_t)(mt + 1) * 128 * 128, t);
            tile_async(aKl, pKl + (size_t)(mt + 1) * 128 * 128, t);
            CP_COMMIT();
        }

        {
            float mx0 = -1e30f, mx1 = -1e30f;
            #pragma unroll
            for (int j = 0; j < 16; ++j) {
                mx0 = fmaxf(mx0, fmaxf(S[j][0], S[j][1]));
                mx1 = fmaxf(mx1, fmaxf(S[j][2], S[j][3]));
            }
            mx0 = fmaxf(mx0, __shfl_xor_sync(0xffffffffu, mx0, 1));
            mx0 = fmaxf(mx0, __shfl_xor_sync(0xffffffffu, mx0, 2));
            mx1 = fmaxf(mx1, __shfl_xor_sync(0xffffffffu, mx1, 1));
            mx1 = fmaxf(mx1, __shfl_xor_sync(0xffffffffu, mx1, 2));
            float mn0 = fmaxf(m0, mx0), mn1 = fmaxf(m1, mx1);
            float a0 = __expf(m0 - mn0), a1 = __expf(m1 - mn1);
            m0 = mn0; m1 = mn1;
            float ls0 = 0.0f, ls1 = 0.0f;
            #pragma unroll
            for (int j = 0; j < 16; ++j) {
                S[j][0] = __expf(S[j][0] - mn0); ls0 += S[j][0];
                S[j][1] = __expf(S[j][1] - mn0); ls0 += S[j][1];
                S[j][2] = __expf(S[j][2] - mn1); ls1 += S[j][2];
                S[j][3] = __expf(S[j][3] - mn1); ls1 += S[j][3];
                O[j][0] *= a0; O[j][1] *= a0; O[j][2] *= a1; O[j][3] *= a1;
            }
            ls0 += __shfl_xor_sync(0xffffffffu, ls0, 1);
            ls0 += __shfl_xor_sync(0xffffffffu, ls0, 2);
            ls1 += __shfl_xor_sync(0xffffffffu, ls1, 1);
            ls1 += __shfl_xor_sync(0xffffffffu, ls1, 2);
            l0 = l0 * a0 + ls0;
            l1 = l1 * a1 + ls1;
        }

        if (mt < 31) { CP_WAIT1(); } else { CP_WAIT0(); }
        __syncthreads();

        #pragma unroll
        for (int kc = 0; kc < 8; ++kc) {
            uint32_t ah[4], al[4];
            split2(S[2 * kc][0],     S[2 * kc][1],     ah[0], al[0]);
            split2(S[2 * kc][2],     S[2 * kc][3],     ah[1], al[1]);
            split2(S[2 * kc + 1][0], S[2 * kc + 1][1], ah[2], al[2]);
            split2(S[2 * kc + 1][2], S[2 * kc + 1][3], ah[3], al[3]);
            #pragma unroll
            for (int og = 0; og < 8; ++og) {
                uint32_t vh[4], vl[4];
                uint32_t ro = (uint32_t)kc * 16 * TPITCH + offV_row + og * 32;
                ldsm4t(vh, aVh + ro);
                ldsm4t(vl, aVl + ro);
                mma_bf16(O[2 * og],     ah, vh[0], vh[1]);
                mma_bf16(O[2 * og + 1], ah, vh[2], vh[3]);
                mma_bf16(O[2 * og],     ah, vl[0], vl[1]);
                mma_bf16(O[2 * og + 1], ah, vl[2], vl[3]);
                mma_bf16(O[2 * og],     al, vh[0], vh[1]);
                mma_bf16(O[2 * og + 1], al, vh[2], vh[3]);
            }
        }
        __syncthreads();

        if (mt < 31) {
            tile_async(aVh, pVh + (size_t)(mt + 1) * 128 * 128, t);
            tile_async(aVl, pVl + (size_t)(mt + 1) * 128 * 128, t);
            CP_COMMIT();
        }
    }

    const float i0 = 1.0f / l0, i1 = 1.0f / l1;
    const int nbase = qt * 128 + n0 + (lane >> 2);
    #pragma unroll
    for (int j = 0; j < 16; ++j) {
        int o = j * 8 + (lane & 3) * 2;
        float* p0 = out + ((size_t)(b * COUT + o)) * NP + nbase;
        float* p1 = out + ((size_t)(b * COUT + o + 1)) * NP + nbase;
        p0[0] = O[j][0] * i0;
        p1[0] = O[j][1] * i0;
        p0[8] = O[j][2] * i1;
        p1[8] = O[j][3] * i1;
    }
}

// ---------------------------------------------------------------------------
extern "C" void kernel_launch(void* const* d_in, const int* in_sizes, int n_in,
                              void* d_out, int out_size)
{
    (void)in_sizes; (void)n_in; (void)out_size;
    const float* x  = (const float*)d_in[0];
    const float* Wq = (const float*)d_in[1];
    const float* bq = (const float*)d_in[2];
    const float* Wk = (const float*)d_in[3];
    const float* bk = (const float*)d_in[4];
    const float* Wv = (const float*)d_in[5];
    const float* bv = (const float*)d_in[6];
    float* out = (float*)d_out;

    cudaFuncSetAttribute(qkv_mma_kernel, cudaFuncAttributeMaxDynamicSharedMemorySize,
                         2 * GSTAGE);
    cudaFuncSetAttribute(attn_kernel, cudaFuncAttributeMaxDynamicSharedMemorySize,
                         6 * TBYTES + 256);

    wsplit_kernel<<<dim3(COUT, 3), 256>>>(Wq, Wk, Wv);
    im2col_kernel<<<dim3(16, CIN, BATCH), 256>>>(x);
    qkv_mma_kernel<<<dim3(32, BATCH, 3), 256, 2 * GSTAGE>>>(bq, bk, bv);
    attn_kernel<<<dim3(32, BATCH), 256, 6 * TBYTES + 256>>>(out);
}

// round 5
// speedup vs baseline: 3.5714x; 1.0143x over previous
#include <cuda_runtime.h>
#include <cuda_bf16.h>
#include <stdint.h>
#include <math.h>

#define CIN   64
#define COUT  128
#define HIN   256
#define WIN   256
#define NP    4096
#define BATCH 4
#define KDIM  1024

// bf16 hi/lo splits: Q, K, V all stored [b][n][o] (row = token, col = channel)
__device__ __align__(128) __nv_bfloat16 gQh[BATCH][NP][COUT];
__device__ __align__(128) __nv_bfloat16 gQl[BATCH][NP][COUT];
__device__ __align__(128) __nv_bfloat16 gKh[BATCH][NP][COUT];
__device__ __align__(128) __nv_bfloat16 gKl[BATCH][NP][COUT];
__device__ __align__(128) __nv_bfloat16 gVh[BATCH][NP][COUT];
__device__ __align__(128) __nv_bfloat16 gVl[BATCH][NP][COUT];
// im2col activations [b][n][ck] and split weights [mat][o][ck]
__device__ __align__(128) __nv_bfloat16 gAh[BATCH][NP][KDIM];
__device__ __align__(128) __nv_bfloat16 gAl[BATCH][NP][KDIM];
__device__ __align__(128) __nv_bfloat16 gWh[3][COUT][KDIM];
__device__ __align__(128) __nv_bfloat16 gWl[3][COUT][KDIM];

// ---------------------------------------------------------------------------
// helpers
// ---------------------------------------------------------------------------
__device__ __forceinline__ uint32_t smem_u32(const void* p) {
    uint32_t a;
    asm("{ .reg .u64 t; cvta.to.shared.u64 t, %1; cvt.u32.u64 %0, t; }" : "=r"(a) : "l"(p));
    return a;
}
__device__ __forceinline__ void ldsm4(uint32_t r[4], uint32_t addr) {
    asm volatile("ldmatrix.sync.aligned.m8n8.x4.shared.b16 {%0,%1,%2,%3}, [%4];"
                 : "=r"(r[0]), "=r"(r[1]), "=r"(r[2]), "=r"(r[3]) : "r"(addr));
}
__device__ __forceinline__ void ldsm4t(uint32_t r[4], uint32_t addr) {
    asm volatile("ldmatrix.sync.aligned.m8n8.x4.trans.shared.b16 {%0,%1,%2,%3}, [%4];"
                 : "=r"(r[0]), "=r"(r[1]), "=r"(r[2]), "=r"(r[3]) : "r"(addr));
}
__device__ __forceinline__ void mma_bf16(float d[4], const uint32_t a[4],
                                         uint32_t b0, uint32_t b1) {
    asm volatile("mma.sync.aligned.m16n8k16.row.col.f32.bf16.bf16.f32 "
                 "{%0,%1,%2,%3}, {%4,%5,%6,%7}, {%8,%9}, {%0,%1,%2,%3};"
                 : "+f"(d[0]), "+f"(d[1]), "+f"(d[2]), "+f"(d[3])
                 : "r"(a[0]), "r"(a[1]), "r"(a[2]), "r"(a[3]), "r"(b0), "r"(b1));
}
__device__ __forceinline__ void cpasync16(uint32_t dst, const void* src) {
    asm volatile("cp.async.cg.shared.global [%0], [%1], 16;" :: "r"(dst), "l"(src));
}
#define CP_COMMIT() asm volatile("cp.async.commit_group;" ::: "memory")
#define CP_WAIT1()  asm volatile("cp.async.wait_group 1;" ::: "memory")
#define CP_WAIT0()  asm volatile("cp.async.wait_group 0;" ::: "memory")

__device__ __forceinline__ uint32_t pack_bf2(__nv_bfloat16 a, __nv_bfloat16 b) {
    return ((uint32_t)__bfloat16_as_ushort(b) << 16) | (uint32_t)__bfloat16_as_ushort(a);
}
__device__ __forceinline__ void split2(float x, float y, uint32_t& h, uint32_t& l) {
    __nv_bfloat16 hx = __float2bfloat16(x), hy = __float2bfloat16(y);
    h = pack_bf2(hx, hy);
    l = pack_bf2(__float2bfloat16(x - __bfloat162float(hx)),
                 __float2bfloat16(y - __bfloat162float(hy)));
}

// ---------------------------------------------------------------------------
// Pass 0a: split W into bf16 hi/lo
// ---------------------------------------------------------------------------
__global__ void wsplit_kernel(const float* __restrict__ Wq,
                              const float* __restrict__ Wk,
                              const float* __restrict__ Wv)
{
    const int o = blockIdx.x, mat = blockIdx.y, t = threadIdx.x;
    const float* W = (mat == 0) ? Wq : (mat == 1) ? Wk : Wv;
    float4 w = *(const float4*)(W + o * KDIM + t * 4);
    uint32_t h0, l0, h1, l1;
    split2(w.x, w.y, h0, l0);
    split2(w.z, w.w, h1, l1);
    *(uint2*)&gWh[mat][o][t * 4] = make_uint2(h0, h1);
    *(uint2*)&gWl[mat][o][t * 4] = make_uint2(l0, l1);
}

// ---------------------------------------------------------------------------
// Pass 0b: im2col + split
// ---------------------------------------------------------------------------
__global__ void im2col_kernel(const float* __restrict__ x)
{
    const int pw = threadIdx.x & 63;
    const int ph = blockIdx.x * 4 + (threadIdx.x >> 6);
    const int c = blockIdx.y, b = blockIdx.z;
    const float* xp = x + (((size_t)(b * CIN + c) * HIN + ph * 4) * WIN + pw * 4);
    uint32_t h[8], l[8];
    #pragma unroll
    for (int kh = 0; kh < 4; ++kh) {
        float4 v = *(const float4*)(xp + kh * WIN);
        split2(v.x, v.y, h[kh * 2], l[kh * 2]);
        split2(v.z, v.w, h[kh * 2 + 1], l[kh * 2 + 1]);
    }
    const int n = ph * 64 + pw;
    *(uint4*)&gAh[b][n][c * 16]     = make_uint4(h[0], h[1], h[2], h[3]);
    *(uint4*)&gAh[b][n][c * 16 + 8] = make_uint4(h[4], h[5], h[6], h[7]);
    *(uint4*)&gAl[b][n][c * 16]     = make_uint4(l[0], l[1], l[2], l[3]);
    *(uint4*)&gAl[b][n][c * 16 + 8] = make_uint4(l[4], l[5], l[6], l[7]);
}

// ---------------------------------------------------------------------------
// Pass 1: QKV GEMM via mma.sync bf16x3. 3-stage cp.async ring, 1 barrier/chunk.
// ---------------------------------------------------------------------------
#define GP 144
#define GTILE (128 * GP)            // 18432 B per tile
#define GSTAGE (4 * GTILE)          // Ah, Al, Wh, Wl

__device__ __forceinline__ void gchunk_async(uint32_t sbase,
                                             const __nv_bfloat16* __restrict__ gA_h,
                                             const __nv_bfloat16* __restrict__ gA_l,
                                             const __nv_bfloat16* __restrict__ gW_h,
                                             const __nv_bfloat16* __restrict__ gW_l,
                                             int kc0, int t)
{
    #pragma unroll
    for (int i = 0; i < 4; ++i) {
        int idx = t + i * 256;
        int row = idx >> 3, cs = idx & 7;
        uint32_t d = sbase + row * GP + cs * 16;
        size_t s = (size_t)row * KDIM + kc0 + cs * 8;
        cpasync16(d,              gA_h + s);
        cpasync16(d + GTILE,      gA_l + s);
        cpasync16(d + 2 * GTILE,  gW_h + s);
        cpasync16(d + 3 * GTILE,  gW_l + s);
    }
}

__global__ __launch_bounds__(256, 1) void qkv_mma_kernel(
    const float* __restrict__ bq, const float* __restrict__ bk,
    const float* __restrict__ bv)
{
    extern __shared__ __align__(128) char sb[];
    const uint32_t s0 = smem_u32(sb);

    const int nt = blockIdx.x, b = blockIdx.y, mat = blockIdx.z;
    const int t = threadIdx.x, lane = t & 31, wid = t >> 5;
    const int n0 = wid * 16;

    const __nv_bfloat16* pAh = &gAh[b][nt * 128][0];
    const __nv_bfloat16* pAl = &gAl[b][nt * 128][0];
    const __nv_bfloat16* pWh = &gWh[mat][0][0];
    const __nv_bfloat16* pWl = &gWl[mat][0][0];
    const float* bias = (mat == 0) ? bq : (mat == 1) ? bk : bv;

    gchunk_async(s0,          pAh, pAl, pWh, pWl, 0, t);
    CP_COMMIT();
    gchunk_async(s0 + GSTAGE, pAh, pAl, pWh, pWl, 64, t);
    CP_COMMIT();

    float S[16][4];
    #pragma unroll
    for (int j = 0; j < 16; ++j)
        #pragma unroll
        for (int c = 0; c < 4; ++c) S[j][c] = 0.0f;

    const uint32_t offA = (uint32_t)(n0 + (lane & 15)) * GP + (lane >> 4) * 16;
    const uint32_t offB = (uint32_t)((lane & 7) + ((lane >> 4) & 1) * 8) * GP +
                          ((lane >> 3) & 1) * 16;

    #pragma unroll 1
    for (int ch = 0; ch < 16; ++ch) {
        if (ch < 15) { CP_WAIT1(); } else { CP_WAIT0(); }
        __syncthreads();
        if (ch < 14) {
            gchunk_async(s0 + ((ch + 2) % 3) * GSTAGE, pAh, pAl, pWh, pWl, (ch + 2) * 64, t);
            CP_COMMIT();
        }
        const uint32_t st = s0 + (ch % 3) * GSTAGE;
        const uint32_t aA = st, aAl = st + GTILE, aW = st + 2 * GTILE, aWl = st + 3 * GTILE;

        #pragma unroll
        for (int kc = 0; kc < 4; ++kc) {
            uint32_t ah[4], al[4];
            ldsm4(ah, aA + offA + kc * 32);
            ldsm4(al, aAl + offA + kc * 32);
            #pragma unroll
            for (int og = 0; og < 8; ++og) {
                uint32_t bh[4], bl[4];
                uint32_t ro = (uint32_t)og * 16 * GP + offB + kc * 32;
                ldsm4(bh, aW + ro);
                ldsm4(bl, aWl + ro);
                mma_bf16(S[2 * og],     ah, bh[0], bh[1]);
                mma_bf16(S[2 * og + 1], ah, bh[2], bh[3]);
                mma_bf16(S[2 * og],     ah, bl[0], bl[1]);
                mma_bf16(S[2 * og + 1], ah, bl[2], bl[3]);
                mma_bf16(S[2 * og],     al, bh[0], bh[1]);
                mma_bf16(S[2 * og + 1], al, bh[2], bh[3]);
            }
        }
    }

    __nv_bfloat16* outh = (mat == 0) ? &gQh[b][0][0] : (mat == 1) ? &gKh[b][0][0] : &gVh[b][0][0];
    __nv_bfloat16* outl = (mat == 0) ? &gQl[b][0][0] : (mat == 1) ? &gKl[b][0][0] : &gVl[b][0][0];
    const int na = nt * 128 + n0 + (lane >> 2);
    #pragma unroll
    for (int j = 0; j < 16; ++j) {
        int o = j * 8 + (lane & 3) * 2;
        float b0 = bias[o], b1 = bias[o + 1];
        uint32_t h, l;
        split2(S[j][0] + b0, S[j][1] + b1, h, l);
        *(uint32_t*)(outh + (size_t)na * COUT + o) = h;
        *(uint32_t*)(outl + (size_t)na * COUT + o) = l;
        split2(S[j][2] + b0, S[j][3] + b1, h, l);
        *(uint32_t*)(outh + (size_t)(na + 8) * COUT + o) = h;
        *(uint32_t*)(outl + (size_t)(na + 8) * COUT + o) = l;
    }
}

// ---------------------------------------------------------------------------
// Phase 2: FlashAttention-2, 64-key tiles, double-buffered K/V, ONE barrier
// per tile (softmax unbracketed so warps drift and keep the tensor pipe fed).
// ---------------------------------------------------------------------------
#define TPITCH 272
#define QBYTES (128 * TPITCH)       // 34816 (Q hi or lo)
#define KTB    (64 * TPITCH)        // 17408 (one 64-row tile)
#define KVSTG  (4 * KTB)            // Kh,Kl,Vh,Vl for one stage
#define ATTN_SMEM (2 * QBYTES + 2 * KVSTG + 256)

// async copy of one 64-key stage: Kh,Kl,Vh,Vl tiles (gmem rows of 128 bf16)
__device__ __forceinline__ void kv_async(uint32_t sbase,
                                         const __nv_bfloat16* __restrict__ pKh,
                                         const __nv_bfloat16* __restrict__ pKl,
                                         const __nv_bfloat16* __restrict__ pVh,
                                         const __nv_bfloat16* __restrict__ pVl,
                                         size_t goff, int t)
{
    #pragma unroll
    for (int i = 0; i < 4; ++i) {
        int idx = t + i * 256;
        int row = idx >> 4, c = idx & 15;
        uint32_t d = sbase + row * TPITCH + c * 16;
        size_t s = goff + (size_t)row * 128 + c * 8;
        cpasync16(d,           pKh + s);
        cpasync16(d + KTB,     pKl + s);
        cpasync16(d + 2 * KTB, pVh + s);
        cpasync16(d + 3 * KTB, pVl + s);
    }
}

__global__ __launch_bounds__(256, 1) void attn_kernel(float* __restrict__ out)
{
    extern __shared__ __align__(128) char sb[];
    const uint32_t aQh = smem_u32(sb);
    const uint32_t aQl = aQh + QBYTES;
    const uint32_t aKV = aQh + 2 * QBYTES;   // two stages of KVSTG

    const int qt = blockIdx.x, b = blockIdx.y;
    const int t = threadIdx.x, lane = t & 31, wid = t >> 5;
    const int n0 = wid * 16;

    const __nv_bfloat16* pKh = &gKh[b][0][0];
    const __nv_bfloat16* pKl = &gKl[b][0][0];
    const __nv_bfloat16* pVh = &gVh[b][0][0];
    const __nv_bfloat16* pVl = &gVl[b][0][0];

    // prefetch stage 0 (tile 0)
    kv_async(aKV, pKh, pKl, pVh, pVl, 0, t);
    CP_COMMIT();

    // load Q (hi/lo) into smem
    {
        const __nv_bfloat16* gq = &gQh[b][qt * 128][0];
        const __nv_bfloat16* gl = &gQl[b][qt * 128][0];
        #pragma unroll
        for (int i = 0; i < 8; ++i) {
            int idx = t + i * 256;
            int row = idx >> 4, c = idx & 15;
            *(uint4*)(sb + row * TPITCH + c * 16) = *(const uint4*)(gq + row * 128 + c * 8);
            *(uint4*)(sb + QBYTES + row * TPITCH + c * 16) = *(const uint4*)(gl + row * 128 + c * 8);
        }
    }

    float S[8][4], O[16][4];
    #pragma unroll
    for (int j = 0; j < 16; ++j)
        #pragma unroll
        for (int c = 0; c < 4; ++c) O[j][c] = 0.0f;
    float m0 = -1e30f, m1 = -1e30f, l0 = 0.0f, l1 = 0.0f;

    const uint32_t offA = (uint32_t)(n0 + (lane & 15)) * TPITCH + (lane >> 4) * 16;
    const uint32_t offB_row = (uint32_t)((lane & 7) + ((lane >> 4) & 1) * 8) * TPITCH +
                              ((lane >> 3) & 1) * 16;
    const uint32_t offV_row = (uint32_t)((lane & 7) + ((lane >> 3) & 1) * 8) * TPITCH +
                              (lane >> 4) * 16;

    #pragma unroll 1
    for (int mt = 0; mt < 64; ++mt) {
        CP_WAIT0();             // tile mt resident (this thread's copies)
        __syncthreads();        // whole tile visible; prev stage fully consumed
        if (mt < 63) {          // prefetch tile mt+1 into the freed stage
            kv_async(aKV + ((mt + 1) & 1) * KVSTG, pKh, pKl, pVh, pVl,
                     (size_t)(mt + 1) * 64 * 128, t);
            CP_COMMIT();
        }
        const uint32_t kb  = aKV + (mt & 1) * KVSTG;
        const uint32_t aKh = kb, aKl = kb + KTB, aVh = kb + 2 * KTB, aVl = kb + 3 * KTB;

        // ---- S = Qh*Kh + Qh*Kl + Ql*Kh  (16q x 64k per warp) ----
        #pragma unroll
        for (int j = 0; j < 8; ++j)
            #pragma unroll
            for (int c = 0; c < 4; ++c) S[j][c] = 0.0f;

        #pragma unroll 1
        for (int kc = 0; kc < 8; ++kc) {
            uint32_t qh[4], ql[4];
            ldsm4(qh, aQh + offA + kc * 32);
            ldsm4(ql, aQl + offA + kc * 32);
            #pragma unroll
            for (int ng = 0; ng < 4; ++ng) {
                uint32_t bh[4], bl[4];
                uint32_t ro = (uint32_t)ng * 16 * TPITCH + offB_row + kc * 32;
                ldsm4(bh, aKh + ro);
                ldsm4(bl, aKl + ro);
                mma_bf16(S[2 * ng],     qh, bh[0], bh[1]);
                mma_bf16(S[2 * ng + 1], qh, bh[2], bh[3]);
                mma_bf16(S[2 * ng],     qh, bl[0], bl[1]);
                mma_bf16(S[2 * ng + 1], qh, bl[2], bl[3]);
                mma_bf16(S[2 * ng],     ql, bh[0], bh[1]);
                mma_bf16(S[2 * ng + 1], ql, bh[2], bh[3]);
            }
        }

        // ---- online softmax (registers only, no barriers) ----
        {
            float mx0 = -1e30f, mx1 = -1e30f;
            #pragma unroll
            for (int j = 0; j < 8; ++j) {
                mx0 = fmaxf(mx0, fmaxf(S[j][0], S[j][1]));
                mx1 = fmaxf(mx1, fmaxf(S[j][2], S[j][3]));
            }
            mx0 = fmaxf(mx0, __shfl_xor_sync(0xffffffffu, mx0, 1));
            mx0 = fmaxf(mx0, __shfl_xor_sync(0xffffffffu, mx0, 2));
            mx1 = fmaxf(mx1, __shfl_xor_sync(0xffffffffu, mx1, 1));
            mx1 = fmaxf(mx1, __shfl_xor_sync(0xffffffffu, mx1, 2));
            float mn0 = fmaxf(m0, mx0), mn1 = fmaxf(m1, mx1);
            float a0 = __expf(m0 - mn0), a1 = __expf(m1 - mn1);
            m0 = mn0; m1 = mn1;
            float ls0 = 0.0f, ls1 = 0.0f;
            #pragma unroll
            for (int j = 0; j < 8; ++j) {
                S[j][0] = __expf(S[j][0] - mn0); ls0 += S[j][0];
                S[j][1] = __expf(S[j][1] - mn0); ls0 += S[j][1];
                S[j][2] = __expf(S[j][2] - mn1); ls1 += S[j][2];
                S[j][3] = __expf(S[j][3] - mn1); ls1 += S[j][3];
            }
            #pragma unroll
            for (int j = 0; j < 16; ++j) {
                O[j][0] *= a0; O[j][1] *= a0; O[j][2] *= a1; O[j][3] *= a1;
            }
            ls0 += __shfl_xor_sync(0xffffffffu, ls0, 1);
            ls0 += __shfl_xor_sync(0xffffffffu, ls0, 2);
            ls1 += __shfl_xor_sync(0xffffffffu, ls1, 1);
            ls1 += __shfl_xor_sync(0xffffffffu, ls1, 2);
            l0 = l0 * a0 + ls0;
            l1 = l1 * a1 + ls1;
        }

        // ---- O += Ph*Vh + Ph*Vl + Pl*Vh ----
        #pragma unroll
        for (int kc = 0; kc < 4; ++kc) {
            uint32_t ah[4], al[4];
            split2(S[2 * kc][0],     S[2 * kc][1],     ah[0], al[0]);
            split2(S[2 * kc][2],     S[2 * kc][3],     ah[1], al[1]);
            split2(S[2 * kc + 1][0], S[2 * kc + 1][1], ah[2], al[2]);
            split2(S[2 * kc + 1][2], S[2 * kc + 1][3], ah[3], al[3]);
            #pragma unroll
            for (int og = 0; og < 8; ++og) {
                uint32_t vh[4], vl[4];
                uint32_t ro = (uint32_t)kc * 16 * TPITCH + offV_row + og * 32;
                ldsm4t(vh, aVh + ro);
                ldsm4t(vl, aVl + ro);
                mma_bf16(O[2 * og],     ah, vh[0], vh[1]);
                mma_bf16(O[2 * og + 1], ah, vh[2], vh[3]);
                mma_bf16(O[2 * og],     ah, vl[0], vl[1]);
                mma_bf16(O[2 * og + 1], ah, vl[2], vl[3]);
                mma_bf16(O[2 * og],     al, vh[0], vh[1]);
                mma_bf16(O[2 * og + 1], al, vh[2], vh[3]);
            }
        }
        // no trailing barrier: top-of-loop barrier protects buffer reuse
    }

    const float i0 = 1.0f / l0, i1 = 1.0f / l1;
    const int nbase = qt * 128 + n0 + (lane >> 2);
    #pragma unroll
    for (int j = 0; j < 16; ++j) {
        int o = j * 8 + (lane & 3) * 2;
        float* p0 = out + ((size_t)(b * COUT + o)) * NP + nbase;
        float* p1 = out + ((size_t)(b * COUT + o + 1)) * NP + nbase;
        p0[0] = O[j][0] * i0;
        p1[0] = O[j][1] * i0;
        p0[8] = O[j][2] * i1;
        p1[8] = O[j][3] * i1;
    }
}

// ---------------------------------------------------------------------------
extern "C" void kernel_launch(void* const* d_in, const int* in_sizes, int n_in,
                              void* d_out, int out_size)
{
    (void)in_sizes; (void)n_in; (void)out_size;
    const float* x  = (const float*)d_in[0];
    const float* Wq = (const float*)d_in[1];
    const float* bq = (const float*)d_in[2];
    const float* Wk = (const float*)d_in[3];
    const float* bk = (const float*)d_in[4];
    const float* Wv = (const float*)d_in[5];
    const float* bv = (const float*)d_in[6];
    float* out = (float*)d_out;

    cudaFuncSetAttribute(qkv_mma_kernel, cudaFuncAttributeMaxDynamicSharedMemorySize,
                         3 * GSTAGE);
    cudaFuncSetAttribute(attn_kernel, cudaFuncAttributeMaxDynamicSharedMemorySize,
                         ATTN_SMEM);

    wsplit_kernel<<<dim3(COUT, 3), 256>>>(Wq, Wk, Wv);
    im2col_kernel<<<dim3(16, CIN, BATCH), 256>>>(x);
    qkv_mma_kernel<<<dim3(32, BATCH, 3), 256, 3 * GSTAGE>>>(bq, bk, bv);
    attn_kernel<<<dim3(32, BATCH), 256, ATTN_SMEM>>>(out);
}

// round 6
// speedup vs baseline: 3.6004x; 1.0081x over previous
#include <cuda_runtime.h>
#include <cuda_bf16.h>
#include <stdint.h>
#include <math.h>

#define CIN   64
#define COUT  128
#define HIN   256
#define WIN   256
#define NP    4096
#define BATCH 4
#define KDIM  1024

// bf16 hi/lo splits: Q, K, V all stored [b][n][o] (row = token, col = channel)
__device__ __align__(128) __nv_bfloat16 gQh[BATCH][NP][COUT];
__device__ __align__(128) __nv_bfloat16 gQl[BATCH][NP][COUT];
__device__ __align__(128) __nv_bfloat16 gKh[BATCH][NP][COUT];
__device__ __align__(128) __nv_bfloat16 gKl[BATCH][NP][COUT];
__device__ __align__(128) __nv_bfloat16 gVh[BATCH][NP][COUT];
__device__ __align__(128) __nv_bfloat16 gVl[BATCH][NP][COUT];
// im2col activations [b][n][ck] and split weights [mat][o][ck]
__device__ __align__(128) __nv_bfloat16 gAh[BATCH][NP][KDIM];
__device__ __align__(128) __nv_bfloat16 gAl[BATCH][NP][KDIM];
__device__ __align__(128) __nv_bfloat16 gWh[3][COUT][KDIM];
__device__ __align__(128) __nv_bfloat16 gWl[3][COUT][KDIM];

// ---------------------------------------------------------------------------
// helpers
// ---------------------------------------------------------------------------
__device__ __forceinline__ uint32_t smem_u32(const void* p) {
    uint32_t a;
    asm("{ .reg .u64 t; cvta.to.shared.u64 t, %1; cvt.u32.u64 %0, t; }" : "=r"(a) : "l"(p));
    return a;
}
__device__ __forceinline__ void ldsm4(uint32_t r[4], uint32_t addr) {
    asm volatile("ldmatrix.sync.aligned.m8n8.x4.shared.b16 {%0,%1,%2,%3}, [%4];"
                 : "=r"(r[0]), "=r"(r[1]), "=r"(r[2]), "=r"(r[3]) : "r"(addr));
}
__device__ __forceinline__ void ldsm4t(uint32_t r[4], uint32_t addr) {
    asm volatile("ldmatrix.sync.aligned.m8n8.x4.trans.shared.b16 {%0,%1,%2,%3}, [%4];"
                 : "=r"(r[0]), "=r"(r[1]), "=r"(r[2]), "=r"(r[3]) : "r"(addr));
}
__device__ __forceinline__ void mma_bf16(float d[4], const uint32_t a[4],
                                         uint32_t b0, uint32_t b1) {
    asm volatile("mma.sync.aligned.m16n8k16.row.col.f32.bf16.bf16.f32 "
                 "{%0,%1,%2,%3}, {%4,%5,%6,%7}, {%8,%9}, {%0,%1,%2,%3};"
                 : "+f"(d[0]), "+f"(d[1]), "+f"(d[2]), "+f"(d[3])
                 : "r"(a[0]), "r"(a[1]), "r"(a[2]), "r"(a[3]), "r"(b0), "r"(b1));
}
__device__ __forceinline__ void cpasync16(uint32_t dst, const void* src) {
    asm volatile("cp.async.cg.shared.global [%0], [%1], 16;" :: "r"(dst), "l"(src));
}
#define CP_COMMIT() asm volatile("cp.async.commit_group;" ::: "memory")
#define CP_WAIT1()  asm volatile("cp.async.wait_group 1;" ::: "memory")
#define CP_WAIT0()  asm volatile("cp.async.wait_group 0;" ::: "memory")

__device__ __forceinline__ uint32_t pack_bf2(__nv_bfloat16 a, __nv_bfloat16 b) {
    return ((uint32_t)__bfloat16_as_ushort(b) << 16) | (uint32_t)__bfloat16_as_ushort(a);
}
__device__ __forceinline__ void split2(float x, float y, uint32_t& h, uint32_t& l) {
    __nv_bfloat16 hx = __float2bfloat16(x), hy = __float2bfloat16(y);
    h = pack_bf2(hx, hy);
    l = pack_bf2(__float2bfloat16(x - __bfloat162float(hx)),
                 __float2bfloat16(y - __bfloat162float(hy)));
}

// ---------------------------------------------------------------------------
// Pass 0a: split W into bf16 hi/lo
// ---------------------------------------------------------------------------
__global__ void wsplit_kernel(const float* __restrict__ Wq,
                              const float* __restrict__ Wk,
                              const float* __restrict__ Wv)
{
    const int o = blockIdx.x, mat = blockIdx.y, t = threadIdx.x;
    const float* W = (mat == 0) ? Wq : (mat == 1) ? Wk : Wv;
    float4 w = *(const float4*)(W + o * KDIM + t * 4);
    uint32_t h0, l0, h1, l1;
    split2(w.x, w.y, h0, l0);
    split2(w.z, w.w, h1, l1);
    *(uint2*)&gWh[mat][o][t * 4] = make_uint2(h0, h1);
    *(uint2*)&gWl[mat][o][t * 4] = make_uint2(l0, l1);
}

// ---------------------------------------------------------------------------
// Pass 0b: im2col + split
// ---------------------------------------------------------------------------
__global__ void im2col_kernel(const float* __restrict__ x)
{
    const int pw = threadIdx.x & 63;
    const int ph = blockIdx.x * 4 + (threadIdx.x >> 6);
    const int c = blockIdx.y, b = blockIdx.z;
    const float* xp = x + (((size_t)(b * CIN + c) * HIN + ph * 4) * WIN + pw * 4);
    uint32_t h[8], l[8];
    #pragma unroll
    for (int kh = 0; kh < 4; ++kh) {
        float4 v = *(const float4*)(xp + kh * WIN);
        split2(v.x, v.y, h[kh * 2], l[kh * 2]);
        split2(v.z, v.w, h[kh * 2 + 1], l[kh * 2 + 1]);
    }
    const int n = ph * 64 + pw;
    *(uint4*)&gAh[b][n][c * 16]     = make_uint4(h[0], h[1], h[2], h[3]);
    *(uint4*)&gAh[b][n][c * 16 + 8] = make_uint4(h[4], h[5], h[6], h[7]);
    *(uint4*)&gAl[b][n][c * 16]     = make_uint4(l[0], l[1], l[2], l[3]);
    *(uint4*)&gAl[b][n][c * 16 + 8] = make_uint4(l[4], l[5], l[6], l[7]);
}

// ---------------------------------------------------------------------------
// Pass 1: QKV GEMM via mma.sync bf16x3. Persistent grid (148), 3-stage ring.
// ---------------------------------------------------------------------------
#define GP 144
#define GTILE (128 * GP)            // 18432 B per tile
#define GSTAGE (4 * GTILE)          // Ah, Al, Wh, Wl
#define NITEMS (32 * BATCH * 3)     // 384 work items

__device__ __forceinline__ void gchunk_async(uint32_t sbase,
                                             const __nv_bfloat16* __restrict__ gA_h,
                                             const __nv_bfloat16* __restrict__ gA_l,
                                             const __nv_bfloat16* __restrict__ gW_h,
                                             const __nv_bfloat16* __restrict__ gW_l,
                                             int kc0, int t)
{
    #pragma unroll
    for (int i = 0; i < 4; ++i) {
        int idx = t + i * 256;
        int row = idx >> 3, cs = idx & 7;
        uint32_t d = sbase + row * GP + cs * 16;
        size_t s = (size_t)row * KDIM + kc0 + cs * 8;
        cpasync16(d,              gA_h + s);
        cpasync16(d + GTILE,      gA_l + s);
        cpasync16(d + 2 * GTILE,  gW_h + s);
        cpasync16(d + 3 * GTILE,  gW_l + s);
    }
}

__global__ __launch_bounds__(256, 1) void qkv_mma_kernel(
    const float* __restrict__ bq, const float* __restrict__ bk,
    const float* __restrict__ bv)
{
    extern __shared__ __align__(128) char sb[];
    const uint32_t s0 = smem_u32(sb);
    const int t = threadIdx.x, lane = t & 31, wid = t >> 5;
    const int n0 = wid * 16;

    const uint32_t offA = (uint32_t)(n0 + (lane & 15)) * GP + (lane >> 4) * 16;
    const uint32_t offB = (uint32_t)((lane & 7) + ((lane >> 4) & 1) * 8) * GP +
                          ((lane >> 3) & 1) * 16;

    for (int item = blockIdx.x; item < NITEMS; item += gridDim.x) {
        const int nt = item & 31, b = (item >> 5) & 3, mat = item >> 7;
        const __nv_bfloat16* pAh = &gAh[b][nt * 128][0];
        const __nv_bfloat16* pAl = &gAl[b][nt * 128][0];
        const __nv_bfloat16* pWh = &gWh[mat][0][0];
        const __nv_bfloat16* pWl = &gWl[mat][0][0];
        const float* bias = (mat == 0) ? bq : (mat == 1) ? bk : bv;

        __syncthreads();    // smem free (previous item fully consumed)
        gchunk_async(s0,          pAh, pAl, pWh, pWl, 0, t);
        CP_COMMIT();
        gchunk_async(s0 + GSTAGE, pAh, pAl, pWh, pWl, 64, t);
        CP_COMMIT();

        float S[16][4];
        #pragma unroll
        for (int j = 0; j < 16; ++j)
            #pragma unroll
            for (int c = 0; c < 4; ++c) S[j][c] = 0.0f;

        #pragma unroll 1
        for (int ch = 0; ch < 16; ++ch) {
            if (ch < 15) { CP_WAIT1(); } else { CP_WAIT0(); }
            __syncthreads();
            if (ch < 14) {
                gchunk_async(s0 + ((ch + 2) % 3) * GSTAGE, pAh, pAl, pWh, pWl, (ch + 2) * 64, t);
                CP_COMMIT();
            }
            const uint32_t st = s0 + (ch % 3) * GSTAGE;
            const uint32_t aA = st, aAl = st + GTILE, aW = st + 2 * GTILE, aWl = st + 3 * GTILE;

            #pragma unroll
            for (int kc = 0; kc < 4; ++kc) {
                uint32_t ah[4], al[4];
                ldsm4(ah, aA + offA + kc * 32);
                ldsm4(al, aAl + offA + kc * 32);
                #pragma unroll
                for (int h = 0; h < 2; ++h) {
                    uint32_t bh[4][4], bl[4][4];
                    #pragma unroll
                    for (int g = 0; g < 4; ++g) {
                        uint32_t ro = (uint32_t)(h * 4 + g) * 16 * GP + offB + kc * 32;
                        ldsm4(bh[g], aW + ro);
                        ldsm4(bl[g], aWl + ro);
                    }
                    #pragma unroll
                    for (int g = 0; g < 4; ++g) {
                        int og = h * 4 + g;
                        mma_bf16(S[2 * og],     ah, bh[g][0], bh[g][1]);
                        mma_bf16(S[2 * og + 1], ah, bh[g][2], bh[g][3]);
                    }
                    #pragma unroll
                    for (int g = 0; g < 4; ++g) {
                        int og = h * 4 + g;
                        mma_bf16(S[2 * og],     ah, bl[g][0], bl[g][1]);
                        mma_bf16(S[2 * og + 1], ah, bl[g][2], bl[g][3]);
                    }
                    #pragma unroll
                    for (int g = 0; g < 4; ++g) {
                        int og = h * 4 + g;
                        mma_bf16(S[2 * og],     al, bh[g][0], bh[g][1]);
                        mma_bf16(S[2 * og + 1], al, bh[g][2], bh[g][3]);
                    }
                }
            }
        }

        __nv_bfloat16* outh = (mat == 0) ? &gQh[b][0][0] : (mat == 1) ? &gKh[b][0][0] : &gVh[b][0][0];
        __nv_bfloat16* outl = (mat == 0) ? &gQl[b][0][0] : (mat == 1) ? &gKl[b][0][0] : &gVl[b][0][0];
        const int na = nt * 128 + n0 + (lane >> 2);
        #pragma unroll
        for (int j = 0; j < 16; ++j) {
            int o = j * 8 + (lane & 3) * 2;
            float b0 = bias[o], b1 = bias[o + 1];
            uint32_t h, l;
            split2(S[j][0] + b0, S[j][1] + b1, h, l);
            *(uint32_t*)(outh + (size_t)na * COUT + o) = h;
            *(uint32_t*)(outl + (size_t)na * COUT + o) = l;
            split2(S[j][2] + b0, S[j][3] + b1, h, l);
            *(uint32_t*)(outh + (size_t)(na + 8) * COUT + o) = h;
            *(uint32_t*)(outl + (size_t)(na + 8) * COUT + o) = l;
        }
    }
}

// ---------------------------------------------------------------------------
// Phase 2: FlashAttention-2, 64-key tiles, double-buffered K/V, 1 barrier/tile,
// inner loops reordered: batch ldmatrix, then grouped independent MMAs.
// ---------------------------------------------------------------------------
#define TPITCH 272
#define QBYTES (128 * TPITCH)       // 34816 (Q hi or lo)
#define KTB    (64 * TPITCH)        // 17408 (one 64-row tile)
#define KVSTG  (4 * KTB)            // Kh,Kl,Vh,Vl for one stage
#define ATTN_SMEM (2 * QBYTES + 2 * KVSTG + 256)

__device__ __forceinline__ void kv_async(uint32_t sbase,
                                         const __nv_bfloat16* __restrict__ pKh,
                                         const __nv_bfloat16* __restrict__ pKl,
                                         const __nv_bfloat16* __restrict__ pVh,
                                         const __nv_bfloat16* __restrict__ pVl,
                                         size_t goff, int t)
{
    #pragma unroll
    for (int i = 0; i < 4; ++i) {
        int idx = t + i * 256;
        int row = idx >> 4, c = idx & 15;
        uint32_t d = sbase + row * TPITCH + c * 16;
        size_t s = goff + (size_t)row * 128 + c * 8;
        cpasync16(d,           pKh + s);
        cpasync16(d + KTB,     pKl + s);
        cpasync16(d + 2 * KTB, pVh + s);
        cpasync16(d + 3 * KTB, pVl + s);
    }
}

__global__ __launch_bounds__(256, 1) void attn_kernel(float* __restrict__ out)
{
    extern __shared__ __align__(128) char sb[];
    const uint32_t aQh = smem_u32(sb);
    const uint32_t aQl = aQh + QBYTES;
    const uint32_t aKV = aQh + 2 * QBYTES;

    const int qt = blockIdx.x, b = blockIdx.y;
    const int t = threadIdx.x, lane = t & 31, wid = t >> 5;
    const int n0 = wid * 16;

    const __nv_bfloat16* pKh = &gKh[b][0][0];
    const __nv_bfloat16* pKl = &gKl[b][0][0];
    const __nv_bfloat16* pVh = &gVh[b][0][0];
    const __nv_bfloat16* pVl = &gVl[b][0][0];

    kv_async(aKV, pKh, pKl, pVh, pVl, 0, t);
    CP_COMMIT();

    {
        const __nv_bfloat16* gq = &gQh[b][qt * 128][0];
        const __nv_bfloat16* gl = &gQl[b][qt * 128][0];
        #pragma unroll
        for (int i = 0; i < 8; ++i) {
            int idx = t + i * 256;
            int row = idx >> 4, c = idx & 15;
            *(uint4*)(sb + row * TPITCH + c * 16) = *(const uint4*)(gq + row * 128 + c * 8);
            *(uint4*)(sb + QBYTES + row * TPITCH + c * 16) = *(const uint4*)(gl + row * 128 + c * 8);
        }
    }

    float S[8][4], O[16][4];
    #pragma unroll
    for (int j = 0; j < 16; ++j)
        #pragma unroll
        for (int c = 0; c < 4; ++c) O[j][c] = 0.0f;
    float m0 = -1e30f, m1 = -1e30f, l0 = 0.0f, l1 = 0.0f;

    const uint32_t offA = (uint32_t)(n0 + (lane & 15)) * TPITCH + (lane >> 4) * 16;
    const uint32_t offB_row = (uint32_t)((lane & 7) + ((lane >> 4) & 1) * 8) * TPITCH +
                              ((lane >> 3) & 1) * 16;
    const uint32_t offV_row = (uint32_t)((lane & 7) + ((lane >> 3) & 1) * 8) * TPITCH +
                              (lane >> 4) * 16;

    #pragma unroll 1
    for (int mt = 0; mt < 64; ++mt) {
        CP_WAIT0();
        __syncthreads();
        if (mt < 63) {
            kv_async(aKV + ((mt + 1) & 1) * KVSTG, pKh, pKl, pVh, pVl,
                     (size_t)(mt + 1) * 64 * 128, t);
            CP_COMMIT();
        }
        const uint32_t kb  = aKV + (mt & 1) * KVSTG;
        const uint32_t aKh = kb, aKl = kb + KTB, aVh = kb + 2 * KTB, aVl = kb + 3 * KTB;

        // ---- S = Qh*Kh + Qh*Kl + Ql*Kh  (batched ldsm, grouped MMAs) ----
        #pragma unroll
        for (int j = 0; j < 8; ++j)
            #pragma unroll
            for (int c = 0; c < 4; ++c) S[j][c] = 0.0f;

        #pragma unroll 1
        for (int kc = 0; kc < 8; ++kc) {
            uint32_t qh[4], ql[4];
            ldsm4(qh, aQh + offA + kc * 32);
            ldsm4(ql, aQl + offA + kc * 32);
            uint32_t bh[4][4], bl[4][4];
            #pragma unroll
            for (int g = 0; g < 4; ++g) {
                uint32_t ro = (uint32_t)g * 16 * TPITCH + offB_row + kc * 32;
                ldsm4(bh[g], aKh + ro);
                ldsm4(bl[g], aKl + ro);
            }
            #pragma unroll
            for (int g = 0; g < 4; ++g) {
                mma_bf16(S[2 * g],     qh, bh[g][0], bh[g][1]);
                mma_bf16(S[2 * g + 1], qh, bh[g][2], bh[g][3]);
            }
            #pragma unroll
            for (int g = 0; g < 4; ++g) {
                mma_bf16(S[2 * g],     qh, bl[g][0], bl[g][1]);
                mma_bf16(S[2 * g + 1], qh, bl[g][2], bl[g][3]);
            }
            #pragma unroll
            for (int g = 0; g < 4; ++g) {
                mma_bf16(S[2 * g],     ql, bh[g][0], bh[g][1]);
                mma_bf16(S[2 * g + 1], ql, bh[g][2], bh[g][3]);
            }
        }

        // ---- online softmax (registers only) ----
        {
            float mx0 = -1e30f, mx1 = -1e30f;
            #pragma unroll
            for (int j = 0; j < 8; ++j) {
                mx0 = fmaxf(mx0, fmaxf(S[j][0], S[j][1]));
                mx1 = fmaxf(mx1, fmaxf(S[j][2], S[j][3]));
            }
            mx0 = fmaxf(mx0, __shfl_xor_sync(0xffffffffu, mx0, 1));
            mx0 = fmaxf(mx0, __shfl_xor_sync(0xffffffffu, mx0, 2));
            mx1 = fmaxf(mx1, __shfl_xor_sync(0xffffffffu, mx1, 1));
            mx1 = fmaxf(mx1, __shfl_xor_sync(0xffffffffu, mx1, 2));
            float mn0 = fmaxf(m0, mx0), mn1 = fmaxf(m1, mx1);
            float a0 = __expf(m0 - mn0), a1 = __expf(m1 - mn1);
            m0 = mn0; m1 = mn1;
            float ls0 = 0.0f, ls1 = 0.0f;
            #pragma unroll
            for (int j = 0; j < 8; ++j) {
                S[j][0] = __expf(S[j][0] - mn0); ls0 += S[j][0];
                S[j][1] = __expf(S[j][1] - mn0); ls0 += S[j][1];
                S[j][2] = __expf(S[j][2] - mn1); ls1 += S[j][2];
                S[j][3] = __expf(S[j][3] - mn1); ls1 += S[j][3];
            }
            #pragma unroll
            for (int j = 0; j < 16; ++j) {
                O[j][0] *= a0; O[j][1] *= a0; O[j][2] *= a1; O[j][3] *= a1;
            }
            ls0 += __shfl_xor_sync(0xffffffffu, ls0, 1);
            ls0 += __shfl_xor_sync(0xffffffffu, ls0, 2);
            ls1 += __shfl_xor_sync(0xffffffffu, ls1, 1);
            ls1 += __shfl_xor_sync(0xffffffffu, ls1, 2);
            l0 = l0 * a0 + ls0;
            l1 = l1 * a1 + ls1;
        }

        // ---- O += Ph*Vh + Ph*Vl + Pl*Vh  (batched ldsm, grouped MMAs) ----
        #pragma unroll
        for (int kc = 0; kc < 4; ++kc) {
            uint32_t ah[4], al[4];
            split2(S[2 * kc][0],     S[2 * kc][1],     ah[0], al[0]);
            split2(S[2 * kc][2],     S[2 * kc][3],     ah[1], al[1]);
            split2(S[2 * kc + 1][0], S[2 * kc + 1][1], ah[2], al[2]);
            split2(S[2 * kc + 1][2], S[2 * kc + 1][3], ah[3], al[3]);
            #pragma unroll
            for (int h = 0; h < 2; ++h) {
                uint32_t vh[4][4], vl[4][4];
                #pragma unroll
                for (int g = 0; g < 4; ++g) {
                    uint32_t ro = (uint32_t)kc * 16 * TPITCH + offV_row + (h * 4 + g) * 32;
                    ldsm4t(vh[g], aVh + ro);
                    ldsm4t(vl[g], aVl + ro);
                }
                #pragma unroll
                for (int g = 0; g < 4; ++g) {
                    int og = h * 4 + g;
                    mma_bf16(O[2 * og],     ah, vh[g][0], vh[g][1]);
                    mma_bf16(O[2 * og + 1], ah, vh[g][2], vh[g][3]);
                }
                #pragma unroll
                for (int g = 0; g < 4; ++g) {
                    int og = h * 4 + g;
                    mma_bf16(O[2 * og],     ah, vl[g][0], vl[g][1]);
                    mma_bf16(O[2 * og + 1], ah, vl[g][2], vl[g][3]);
                }
                #pragma unroll
                for (int g = 0; g < 4; ++g) {
                    int og = h * 4 + g;
                    mma_bf16(O[2 * og],     al, vh[g][0], vh[g][1]);
                    mma_bf16(O[2 * og + 1], al, vh[g][2], vh[g][3]);
                }
            }
        }
    }

    const float i0 = 1.0f / l0, i1 = 1.0f / l1;
    const int nbase = qt * 128 + n0 + (lane >> 2);
    #pragma unroll
    for (int j = 0; j < 16; ++j) {
        int o = j * 8 + (lane & 3) * 2;
        float* p0 = out + ((size_t)(b * COUT + o)) * NP + nbase;
        float* p1 = out + ((size_t)(b * COUT + o + 1)) * NP + nbase;
        p0[0] = O[j][0] * i0;
        p1[0] = O[j][1] * i0;
        p0[8] = O[j][2] * i1;
        p1[8] = O[j][3] * i1;
    }
}

// ---------------------------------------------------------------------------
extern "C" void kernel_launch(void* const* d_in, const int* in_sizes, int n_in,
                              void* d_out, int out_size)
{
    (void)in_sizes; (void)n_in; (void)out_size;
    const float* x  = (const float*)d_in[0];
    const float* Wq = (const float*)d_in[1];
    const float* bq = (const float*)d_in[2];
    const float* Wk = (const float*)d_in[3];
    const float* bk = (const float*)d_in[4];
    const float* Wv = (const float*)d_in[5];
    const float* bv = (const float*)d_in[6];
    float* out = (float*)d_out;

    cudaFuncSetAttribute(qkv_mma_kernel, cudaFuncAttributeMaxDynamicSharedMemorySize,
                         3 * GSTAGE);
    cudaFuncSetAttribute(attn_kernel, cudaFuncAttributeMaxDynamicSharedMemorySize,
                         ATTN_SMEM);

    wsplit_kernel<<<dim3(COUT, 3), 256>>>(Wq, Wk, Wv);
    im2col_kernel<<<dim3(16, CIN, BATCH), 256>>>(x);
    qkv_mma_kernel<<<148, 256, 3 * GSTAGE>>>(bq, bk, bv);
    attn_kernel<<<dim3(32, BATCH), 256, ATTN_SMEM>>>(out);
}